// round 12
// baseline (speedup 1.0000x reference)
#include <cuda_runtime.h>
#include <cuda_bf16.h>
#include <cuda_fp16.h>
#include <math.h>
#include <stdint.h>

#define BATCH 4
#define CCH   512
#define HW    4096

typedef __nv_bfloat16 bf16;
typedef __half fp16;

// ---------------- scratch (static __device__ — no allocation allowed) -------
__device__ float g_mean_cc[BATCH*CCH];
__device__ float g_inv_cc [BATCH*CCH];
__device__ float g_mean_ss[BATCH*CCH];
__device__ float g_inv_ss [BATCH*CCH];
__device__ float g_b1p[BATCH*CCH];
__device__ float g_b2p[BATCH*CCH];
__device__ float g_M  [BATCH*HW];        // per-row score max

__device__ bf16 g_W1h[BATCH*CCH*CCH], g_W1l[BATCH*CCH*CCH];
__device__ bf16 g_W2h[BATCH*CCH*CCH], g_W2l[BATCH*CCH*CCH];
__device__ fp16 g_w3h[CCH*CCH],       g_w3l[CCH*CCH];
__device__ fp16 g_wrh[CCH*CCH],       g_wrl[CCH*CCH];

__device__ bf16 g_Xch[(size_t)BATCH*HW*CCH], g_Xcl[(size_t)BATCH*HW*CCH];
__device__ bf16 g_Xsh[(size_t)BATCH*HW*CCH], g_Xsl[(size_t)BATCH*HW*CCH];
__device__ fp16 g_Xsf[(size_t)BATCH*HW*CCH];
__device__ bf16 g_Qh [(size_t)BATCH*HW*CCH], g_Ql [(size_t)BATCH*HW*CCH];
__device__ bf16 g_Kh [(size_t)BATCH*HW*CCH], g_Kl [(size_t)BATCH*HW*CCH];
__device__ fp16 g_Vf [(size_t)BATCH*CCH*HW];                 // V^T fp16 single
__device__ fp16 g_Of [(size_t)BATCH*HW*CCH];                 // O fp16
__device__ fp16 g_Af [(size_t)BATCH*HW*HW];                  // softmax(A) fp16
__device__ float g_S [(size_t)BATCH*HW*HW];                  // fp32 scores

// ---------------- small helpers ----------------------------------------------
__device__ __forceinline__ float warpSum(float v) {
    #pragma unroll
    for (int o = 16; o > 0; o >>= 1) v += __shfl_down_sync(0xffffffffu, v, o);
    return v;
}
__device__ __forceinline__ uint32_t smem_u32(const void* p) {
    uint32_t a;
    asm("{ .reg .u64 t; cvta.to.shared.u64 t, %1; cvt.u32.u64 %0, t; }" : "=r"(a) : "l"(p));
    return a;
}
__device__ __forceinline__ void split_bf16(float v, bf16 &hi, bf16 &lo) {
    hi = __float2bfloat16_rn(v);
    lo = __float2bfloat16_rn(v - __bfloat162float(hi));
}
__device__ __forceinline__ void split_fp16(float v, fp16 &hi, fp16 &lo) {
    hi = __float2half_rn(v);
    lo = __float2half_rn(v - __half2float(hi));
}
__device__ __forceinline__ void atomMaxF(float* a, float v) {
    if (v >= 0.f) atomicMax((int*)a, __float_as_int(v));
    else          atomicMin((unsigned int*)a, __float_as_uint(v));
}

// ---------------- MMA primitives (baseline PTX, no 'a' features) -------------
__device__ __forceinline__ void ldsm4(uint32_t* r, uint32_t addr) {
    asm volatile("ldmatrix.sync.aligned.m8n8.x4.shared.b16 {%0,%1,%2,%3}, [%4];"
        : "=r"(r[0]), "=r"(r[1]), "=r"(r[2]), "=r"(r[3]) : "r"(addr));
}
__device__ __forceinline__ void mma_bf16(float* c, const uint32_t* a,
                                         uint32_t b0, uint32_t b1) {
    asm volatile(
        "mma.sync.aligned.m16n8k16.row.col.f32.bf16.bf16.f32 "
        "{%0,%1,%2,%3}, {%4,%5,%6,%7}, {%8,%9}, {%0,%1,%2,%3};"
        : "+f"(c[0]), "+f"(c[1]), "+f"(c[2]), "+f"(c[3])
        : "r"(a[0]), "r"(a[1]), "r"(a[2]), "r"(a[3]), "r"(b0), "r"(b1));
}
__device__ __forceinline__ void mma_fp16(float* c, const uint32_t* a,
                                         uint32_t b0, uint32_t b1) {
    asm volatile(
        "mma.sync.aligned.m16n8k16.row.col.f32.f16.f16.f32 "
        "{%0,%1,%2,%3}, {%4,%5,%6,%7}, {%8,%9}, {%0,%1,%2,%3};"
        : "+f"(c[0]), "+f"(c[1]), "+f"(c[2]), "+f"(c[3])
        : "r"(a[0]), "r"(a[1]), "r"(a[2]), "r"(a[3]), "r"(b0), "r"(b1));
}
__device__ __forceinline__ void cp16(uint32_t saddr, const void* g) {
    asm volatile("cp.async.cg.shared.global [%0], [%1], 16;"
                 :: "r"(saddr), "l"(g) : "memory");
}
#define CP_COMMIT() asm volatile("cp.async.commit_group;" ::: "memory")
#define CP_WAIT0()  asm volatile("cp.async.wait_group 0;" ::: "memory")

// ---------------- instance-norm stats ---------------------------------------
__global__ __launch_bounds__(256) void stats_kernel(
    const float* __restrict__ x, float* __restrict__ mean, float* __restrict__ inv)
{
    int row = blockIdx.x;
    const float* p = x + (size_t)row * HW;
    float s = 0.f, sq = 0.f;
    for (int i = threadIdx.x; i < HW; i += 256) { float v = p[i]; s += v; sq += v * v; }
    s = warpSum(s); sq = warpSum(sq);
    __shared__ float ss[8], ssq[8];
    int w = threadIdx.x >> 5, lane = threadIdx.x & 31;
    if (lane == 0) { ss[w] = s; ssq[w] = sq; }
    __syncthreads();
    if (threadIdx.x == 0) {
        float S = 0.f, SQ = 0.f;
        #pragma unroll
        for (int i = 0; i < 8; i++) { S += ss[i]; SQ += ssq[i]; }
        float m = S / (float)HW;
        float var = (SQ - (float)HW * m * m) / (float)(HW - 1);
        mean[row] = m;
        inv[row]  = rsqrtf(var + 1e-5f);
    }
}

// ---------------- fold inst-norm into conv weights ---------------------------
__global__ __launch_bounds__(128) void fold_kernel(
    const float* __restrict__ W, const float* __restrict__ bias,
    const float* __restrict__ mean, const float* __restrict__ inv,
    bf16* __restrict__ Wh, bf16* __restrict__ Wl, float* __restrict__ bp)
{
    int o = blockIdx.x, b = blockIdx.y;
    const float* mr = mean + b * CCH;
    const float* ir = inv  + b * CCH;
    float part = 0.f;
    for (int c = threadIdx.x; c < CCH; c += 128) {
        float w  = W[o * CCH + c];
        float iv = ir[c];
        float wp = w * iv;
        bf16 hi, lo; split_bf16(wp, hi, lo);
        size_t idx = ((size_t)b * CCH + o) * CCH + c;
        Wh[idx] = hi; Wl[idx] = lo;
        part += w * mr[c] * iv;
    }
    part = warpSum(part);
    __shared__ float sp[4];
    int w = threadIdx.x >> 5, lane = threadIdx.x & 31;
    if (lane == 0) sp[w] = part;
    __syncthreads();
    if (threadIdx.x == 0) bp[b * CCH + o] = bias[o] - (sp[0] + sp[1] + sp[2] + sp[3]);
}

__global__ __launch_bounds__(256) void split_kernel_fp(
    const float* __restrict__ W, fp16* __restrict__ Wh, fp16* __restrict__ Wl, int n)
{
    int i = blockIdx.x * 256 + threadIdx.x;
    if (i < n) { fp16 hi, lo; split_fp16(W[i], hi, lo); Wh[i] = hi; Wl[i] = lo; }
}

__global__ __launch_bounds__(256) void init_rowmax(float* __restrict__ M) {
    M[blockIdx.x * 256 + threadIdx.x] = -INFINITY;
}

// ---------------- transpose + split ------------------------------------------
template<int FP16OUT>
__global__ __launch_bounds__(256) void transpose_split(
    const float* __restrict__ X, bf16* __restrict__ Th, bf16* __restrict__ Tl,
    fp16* __restrict__ Tf)
{
    int b = blockIdx.z;
    X  += (size_t)b * CCH * HW;
    Th += (size_t)b * HW * CCH;
    Tl += (size_t)b * HW * CCH;
    if (FP16OUT) Tf += (size_t)b * HW * CCH;
    __shared__ float t[32][33];
    int p0 = blockIdx.x * 32, c0 = blockIdx.y * 32;
    int tx = threadIdx.x & 31, ty = threadIdx.x >> 5;
    #pragma unroll
    for (int j = 0; j < 4; j++) {
        int cl = ty * 4 + j;
        t[cl][tx] = X[(size_t)(c0 + cl) * HW + p0 + tx];
    }
    __syncthreads();
    #pragma unroll
    for (int j = 0; j < 4; j++) {
        int pl = ty * 4 + j;
        float v = t[tx][pl];
        bf16 hi, lo; split_bf16(v, hi, lo);
        size_t idx = (size_t)(p0 + pl) * CCH + c0 + tx;
        Th[idx] = hi; Tl[idx] = lo;
        if (FP16OUT) Tf[idx] = __float2half_rn(v);
    }
}

// ============= GEMM geometry: block 128x128, 4 warps (2x2), warp 64x64 ======
#define KTILE 32
#define SROW  80
#define ABYTES (128 * SROW)
#define BUFB4 (4 * ABYTES)
#define SMEM4 (2 * BUFB4)
#define BUFB3 (3 * ABYTES)
#define SMEM3 (2 * BUFB3)
#define BUFB2 (2 * ABYTES)
#define SMEM2 (2 * BUFB2)

// ============= bf16 3-term NT GEMM ==========================================
// EPI: 1 bias[n] + bf16 hi/lo; 7 fp32 C + row-max atomics
template<int EPI>
__global__ __launch_bounds__(128) void hgemm(
    const bf16* __restrict__ Ah, const bf16* __restrict__ Al,
    const bf16* __restrict__ Bh, const bf16* __restrict__ Bl,
    int Kpass, size_t sA, size_t sB,
    float* __restrict__ C, size_t sC,
    bf16* __restrict__ Chi, bf16* __restrict__ Clo, size_t sCh,
    int ldc,
    const float* __restrict__ bias, size_t sBias,
    float* __restrict__ Mrow)
{
    extern __shared__ __align__(16) char smem[];
    const int tid  = threadIdx.x;
    const int wid  = tid >> 5, lane = tid & 31;
    const int wm   = wid >> 1, wn = wid & 1;      // 2 x 2 warp grid, 64x64 tiles
    const int bz   = blockIdx.z;
    const int m0   = blockIdx.y * 128;
    const int n0   = blockIdx.x * 128;

    const char* gAh = (const char*)(Ah + bz * sA);
    const char* gAl = (const char*)(Al + bz * sA);
    const char* gBh = (const char*)(Bh + bz * sB);
    const char* gBl = (const char*)(Bl + bz * sB);
    const size_t rowB = (size_t)Kpass * 2;

    const uint32_t sb = smem_u32(smem);
    // 512 data chunks (16B) per tile; 128 threads -> 4 chunks/thread/tile
    int rr[4], cc4[4];
    uint32_t soff[4];
    #pragma unroll
    for (int j = 0; j < 4; j++) {
        int c = tid + 128 * j;
        rr[j] = c >> 2; cc4[j] = (c & 3) * 16;
        soff[j] = (uint32_t)(rr[j] * SROW + cc4[j]);
    }

    auto issue = [&](int t, int buf) {
        const size_t kb = (size_t)t * (KTILE * 2);
        const uint32_t s = sb + buf * BUFB4;
        #pragma unroll
        for (int j = 0; j < 4; j++) {
            const size_t ga = (size_t)(m0 + rr[j]) * rowB + kb + cc4[j];
            const size_t gb = (size_t)(n0 + rr[j]) * rowB + kb + cc4[j];
            cp16(s            + soff[j], gAh + ga);
            cp16(s +   ABYTES + soff[j], gAl + ga);
            cp16(s + 2*ABYTES + soff[j], gBh + gb);
            cp16(s + 3*ABYTES + soff[j], gBl + gb);
        }
        CP_COMMIT();
    };

    float acc[4][8][4];
    #pragma unroll
    for (int i = 0; i < 4; i++)
        #pragma unroll
        for (int j = 0; j < 8; j++)
            #pragma unroll
            for (int q = 0; q < 4; q++) acc[i][j][q] = 0.f;

    const int nt = Kpass / KTILE;
    const int lr = lane & 15, lc = (lane >> 4) * 16;

    issue(0, 0);
    for (int t = 0; t < nt; t++) {
        const int buf = t & 1;
        CP_WAIT0();
        __syncthreads();
        if (t + 1 < nt) issue(t + 1, buf ^ 1);

        const uint32_t aH = sb + buf * BUFB4;
        const uint32_t aL = aH + ABYTES;
        const uint32_t bH = aH + 2 * ABYTES;
        const uint32_t bL = aH + 3 * ABYTES;

        #pragma unroll
        for (int ks = 0; ks < 2; ks++) {
            const int kof = ks * 32;
            uint32_t bh[4][4], bl[4][4];
            #pragma unroll
            for (int p = 0; p < 4; p++) {
                uint32_t off = (uint32_t)((wn * 64 + p * 16 + lr) * SROW + kof + lc);
                ldsm4(bh[p], bH + off);
                ldsm4(bl[p], bL + off);
            }
            #pragma unroll
            for (int mt = 0; mt < 4; mt++) {
                uint32_t ah[4], al[4];
                uint32_t off = (uint32_t)((wm * 64 + mt * 16 + lr) * SROW + kof + lc);
                ldsm4(ah, aH + off);
                ldsm4(al, aL + off);
                #pragma unroll
                for (int ntl = 0; ntl < 8; ntl++) {
                    const int p = ntl >> 1, h = ntl & 1;
                    mma_bf16(acc[mt][ntl], ah, bh[p][h], bh[p][h + 2]);
                    mma_bf16(acc[mt][ntl], ah, bl[p][h], bl[p][h + 2]);
                    mma_bf16(acc[mt][ntl], al, bh[p][h], bh[p][h + 2]);
                }
            }
        }
    }

    // ---- epilogue ----
    const int n_base = n0 + wn * 64;
    const int m_base = m0 + wm * 64;
    if (EPI == 7) {
        #pragma unroll
        for (int mt = 0; mt < 4; mt++) {
            #pragma unroll
            for (int half = 0; half < 2; half++) {
                const int m = m_base + mt * 16 + (lane >> 2) + half * 8;
                float mx = -INFINITY;
                #pragma unroll
                for (int ntl = 0; ntl < 8; ntl++) {
                    const int n = n_base + ntl * 8 + 2 * (lane & 3);
                    float v0 = acc[mt][ntl][half * 2 + 0];
                    float v1 = acc[mt][ntl][half * 2 + 1];
                    *(float2*)(C + bz * sC + (size_t)m * ldc + n) = make_float2(v0, v1);
                    mx = fmaxf(mx, fmaxf(v0, v1));
                }
                mx = fmaxf(mx, __shfl_xor_sync(0xffffffffu, mx, 1));
                mx = fmaxf(mx, __shfl_xor_sync(0xffffffffu, mx, 2));
                if ((lane & 3) == 0) atomMaxF(Mrow + (size_t)bz * HW + m, mx);
            }
        }
    } else {
        #pragma unroll
        for (int ntl = 0; ntl < 8; ntl++) {
            const int n = n_base + ntl * 8 + 2 * (lane & 3);
            float bn0 = bias[bz * sBias + n];
            float bn1 = bias[bz * sBias + n + 1];
            #pragma unroll
            for (int mt = 0; mt < 4; mt++) {
                #pragma unroll
                for (int half = 0; half < 2; half++) {
                    const int m = m_base + mt * 16 + (lane >> 2) + half * 8;
                    float v0 = acc[mt][ntl][half * 2 + 0] + bn0;
                    float v1 = acc[mt][ntl][half * 2 + 1] + bn1;
                    bf16 h0, l0, h1, l1;
                    split_bf16(v0, h0, l0); split_bf16(v1, h1, l1);
                    __nv_bfloat162 hp; hp.x = h0; hp.y = h1;
                    __nv_bfloat162 lp; lp.x = l0; lp.y = l1;
                    *(__nv_bfloat162*)(Chi + bz * sCh + (size_t)m * ldc + n) = hp;
                    *(__nv_bfloat162*)(Clo + bz * sCh + (size_t)m * ldc + n) = lp;
                }
            }
        }
    }
}

// ============= fp16 NT GEMM =================================================
// MODE 1: A fp16 hi/lo, B single fp16 (2 terms); MODE 2: single x single (1)
// EPI: 4 bias[m] + resid + fp32; 6 fp16 single; 8 bias[m] + fp16 single
template<int EPI, int MODE>
__global__ __launch_bounds__(128) void hgemm16(
    const fp16* __restrict__ A0, const fp16* __restrict__ A1,
    const fp16* __restrict__ B0,
    int Kpass, size_t sA, size_t sB,
    float* __restrict__ C, size_t sC,
    fp16* __restrict__ Cf, size_t sCf,
    int ldc,
    const float* __restrict__ bias, size_t sBias,
    const float* __restrict__ resid, size_t sResid)
{
    extern __shared__ __align__(16) char smem[];
    constexpr int NTILES = (MODE == 2) ? 2 : 3;
    constexpr int BUFB = NTILES * ABYTES;

    const int tid  = threadIdx.x;
    const int wid  = tid >> 5, lane = tid & 31;
    const int wm   = wid >> 1, wn = wid & 1;
    const int bz   = blockIdx.z;
    const int m0   = blockIdx.y * 128;
    const int n0   = blockIdx.x * 128;

    const char* gA0 = (const char*)(A0 + bz * sA);
    const char* gA1 = (MODE == 1) ? (const char*)(A1 + bz * sA) : nullptr;
    const char* gB0 = (const char*)(B0 + bz * sB);
    const size_t rowB = (size_t)Kpass * 2;

    const uint32_t sb = smem_u32(smem);
    int rr[4], cc4[4];
    uint32_t soff[4];
    #pragma unroll
    for (int j = 0; j < 4; j++) {
        int c = tid + 128 * j;
        rr[j] = c >> 2; cc4[j] = (c & 3) * 16;
        soff[j] = (uint32_t)(rr[j] * SROW + cc4[j]);
    }

    auto issue = [&](int t, int buf) {
        const size_t kb = (size_t)t * (KTILE * 2);
        const uint32_t s = sb + buf * BUFB;
        #pragma unroll
        for (int j = 0; j < 4; j++) {
            const size_t ga = (size_t)(m0 + rr[j]) * rowB + kb + cc4[j];
            const size_t gb = (size_t)(n0 + rr[j]) * rowB + kb + cc4[j];
            cp16(s + soff[j], gA0 + ga);
            if (MODE == 1) {
                cp16(s +   ABYTES + soff[j], gA1 + ga);
                cp16(s + 2*ABYTES + soff[j], gB0 + gb);
            } else {
                cp16(s +   ABYTES + soff[j], gB0 + gb);
            }
        }
        CP_COMMIT();
    };

    float acc[4][8][4];
    #pragma unroll
    for (int i = 0; i < 4; i++)
        #pragma unroll
        for (int j = 0; j < 8; j++)
            #pragma unroll
            for (int q = 0; q < 4; q++) acc[i][j][q] = 0.f;

    const int nt = Kpass / KTILE;
    const int lr = lane & 15, lc = (lane >> 4) * 16;

    issue(0, 0);
    for (int t = 0; t < nt; t++) {
        const int buf = t & 1;
        CP_WAIT0();
        __syncthreads();
        if (t + 1 < nt) issue(t + 1, buf ^ 1);

        const uint32_t s0 = sb + buf * BUFB;
        const uint32_t s1 = s0 + ABYTES;
        const uint32_t s2 = s0 + 2 * ABYTES;
        const uint32_t bT = (MODE == 1) ? s2 : s1;

        #pragma unroll
        for (int ks = 0; ks < 2; ks++) {
            const int kof = ks * 32;
            uint32_t bf_[4][4];
            #pragma unroll
            for (int p = 0; p < 4; p++) {
                uint32_t off = (uint32_t)((wn * 64 + p * 16 + lr) * SROW + kof + lc);
                ldsm4(bf_[p], bT + off);
            }
            #pragma unroll
            for (int mt = 0; mt < 4; mt++) {
                uint32_t off = (uint32_t)((wm * 64 + mt * 16 + lr) * SROW + kof + lc);
                if (MODE == 1) {
                    uint32_t ah[4], al[4];
                    ldsm4(ah, s0 + off);
                    ldsm4(al, s1 + off);
                    #pragma unroll
                    for (int ntl = 0; ntl < 8; ntl++) {
                        const int p = ntl >> 1, h = ntl & 1;
                        mma_fp16(acc[mt][ntl], ah, bf_[p][h], bf_[p][h + 2]);
                        mma_fp16(acc[mt][ntl], al, bf_[p][h], bf_[p][h + 2]);
                    }
                } else {
                    uint32_t af[4];
                    ldsm4(af, s0 + off);
                    #pragma unroll
                    for (int ntl = 0; ntl < 8; ntl++) {
                        const int p = ntl >> 1, h = ntl & 1;
                        mma_fp16(acc[mt][ntl], af, bf_[p][h], bf_[p][h + 2]);
                    }
                }
            }
        }
    }

    // ---- epilogue ----
    const int n_base = n0 + wn * 64;
    const int m_base = m0 + wm * 64;
    #pragma unroll
    for (int ntl = 0; ntl < 8; ntl++) {
        const int n = n_base + ntl * 8 + 2 * (lane & 3);
        #pragma unroll
        for (int mt = 0; mt < 4; mt++) {
            #pragma unroll
            for (int half = 0; half < 2; half++) {
                const int m = m_base + mt * 16 + (lane >> 2) + half * 8;
                float v0 = acc[mt][ntl][half * 2 + 0];
                float v1 = acc[mt][ntl][half * 2 + 1];
                if (EPI == 4) {
                    float bm = bias[bz * sBias + m];
                    const float* rp = resid + bz * sResid + (size_t)m * ldc + n;
                    v0 += bm + rp[0]; v1 += bm + rp[1];
                    *(float2*)(C + bz * sC + (size_t)m * ldc + n) = make_float2(v0, v1);
                } else if (EPI == 8) {
                    float bm = bias[bz * sBias + m];
                    __half2 o;
                    o.x = __float2half_rn(v0 + bm); o.y = __float2half_rn(v1 + bm);
                    *(__half2*)(Cf + bz * sCf + (size_t)m * ldc + n) = o;
                } else { // EPI == 6
                    __half2 o; o.x = __float2half_rn(v0); o.y = __float2half_rn(v1);
                    *(__half2*)(Cf + bz * sCf + (size_t)m * ldc + n) = o;
                }
            }
        }
    }
}

// ---------------- streaming softmax: S fp32 + rowmax -> fp16 A ---------------
__global__ __launch_bounds__(256) void softmax_stream(
    const float* __restrict__ S, const float* __restrict__ M, fp16* __restrict__ Af)
{
    const size_t row = blockIdx.x;
    const float* p = S + row * HW;
    fp16* a = Af + row * HW;
    const float mx = M[row];
    int tid = threadIdx.x;
    float vals[16];
    float s = 0.f;
    #pragma unroll
    for (int i = 0; i < 16; i++) {
        vals[i] = __expf(p[tid + i * 256] - mx);
        s += vals[i];
    }
    s = warpSum(s);
    __shared__ float sh[8];
    int w = tid >> 5, lane = tid & 31;
    if (lane == 0) sh[w] = s;
    __syncthreads();
    if (w == 0) {
        float v = (lane < 8) ? sh[lane] : 0.f;
        v = warpSum(v);
        if (lane == 0) sh[0] = v;
    }
    __syncthreads();
    const float invs = 1.f / sh[0];
    #pragma unroll
    for (int i = 0; i < 16; i++)
        a[tid + i * 256] = __float2half_rn(vals[i] * invs);
}

// ---------------- launch -----------------------------------------------------
extern "C" void kernel_launch(void* const* d_in, const int* in_sizes, int n_in,
                              void* d_out, int out_size)
{
    const float* x_fcc = (const float*)d_in[0];
    const float* x_fss = (const float*)d_in[1];
    const float* w1  = (const float*)d_in[2];
    const float* b1  = (const float*)d_in[3];
    const float* w2  = (const float*)d_in[4];
    const float* b2  = (const float*)d_in[5];
    const float* w3  = (const float*)d_in[6];
    const float* b3  = (const float*)d_in[7];
    const float* wrs = (const float*)d_in[8];
    const float* brs = (const float*)d_in[9];
    float* out = (float*)d_out;

    #define SYM(p, s) void* p##_; cudaGetSymbolAddress(&p##_, s); auto p = (decltype(&s[0]))p##_;
    SYM(pMcc, g_mean_cc) SYM(pIcc, g_inv_cc) SYM(pMss, g_mean_ss) SYM(pIss, g_inv_ss)
    SYM(pB1, g_b1p) SYM(pB2, g_b2p) SYM(pM, g_M)
    SYM(pW1h, g_W1h) SYM(pW1l, g_W1l) SYM(pW2h, g_W2h) SYM(pW2l, g_W2l)
    SYM(pw3h, g_w3h) SYM(pw3l, g_w3l) SYM(pwrh, g_wrh) SYM(pwrl, g_wrl)
    SYM(pXch, g_Xch) SYM(pXcl, g_Xcl) SYM(pXsh, g_Xsh) SYM(pXsl, g_Xsl) SYM(pXsf, g_Xsf)
    SYM(pQh, g_Qh) SYM(pQl, g_Ql) SYM(pKh, g_Kh) SYM(pKl, g_Kl)
    SYM(pVf, g_Vf) SYM(pOf, g_Of) SYM(pAf, g_Af) SYM(pS, g_S)
    #undef SYM

    cudaFuncSetAttribute(hgemm<1>, cudaFuncAttributeMaxDynamicSharedMemorySize, SMEM4);
    cudaFuncSetAttribute(hgemm<7>, cudaFuncAttributeMaxDynamicSharedMemorySize, SMEM4);
    cudaFuncSetAttribute((const void*)hgemm16<8,1>, cudaFuncAttributeMaxDynamicSharedMemorySize, SMEM3);
    cudaFuncSetAttribute((const void*)hgemm16<4,1>, cudaFuncAttributeMaxDynamicSharedMemorySize, SMEM3);
    cudaFuncSetAttribute((const void*)hgemm16<6,2>, cudaFuncAttributeMaxDynamicSharedMemorySize, SMEM2);

    // 1) instance-norm stats + rowmax init
    stats_kernel<<<BATCH * CCH, 256>>>(x_fcc, pMcc, pIcc);
    stats_kernel<<<BATCH * CCH, 256>>>(x_fss, pMss, pIss);
    init_rowmax<<<BATCH * HW / 256, 256>>>(pM);

    // 2) fold norm into W1/W2; split w3, wrs (fp16)
    fold_kernel<<<dim3(CCH, BATCH), 128>>>(w1, b1, pMcc, pIcc, pW1h, pW1l, pB1);
    fold_kernel<<<dim3(CCH, BATCH), 128>>>(w2, b2, pMss, pIss, pW2h, pW2l, pB2);
    split_kernel_fp<<<CCH * CCH / 256, 256>>>(w3,  pw3h, pw3l, CCH * CCH);
    split_kernel_fp<<<CCH * CCH / 256, 256>>>(wrs, pwrh, pwrl, CCH * CCH);

    // 3) transpose + split inputs
    transpose_split<0><<<dim3(HW / 32, CCH / 32, BATCH), 256>>>(x_fcc, pXch, pXcl, nullptr);
    transpose_split<1><<<dim3(HW / 32, CCH / 32, BATCH), 256>>>(x_fss, pXsh, pXsl, pXsf);

    const size_t sX = (size_t)HW * CCH;
    const size_t sW = (size_t)CCH * CCH;
    const size_t sS = (size_t)HW * HW;
    const size_t sV = (size_t)CCH * HW;

    // 4) Q, K (bf16 3-term, bf16 hi/lo out)
    hgemm<1><<<dim3(CCH/128, HW/128, BATCH), 128, SMEM4>>>(
        pXch, pXcl, pW1h, pW1l, CCH, sX, sW,
        nullptr, 0, pQh, pQl, sX, CCH, pB1, CCH, nullptr);
    hgemm<1><<<dim3(CCH/128, HW/128, BATCH), 128, SMEM4>>>(
        pXsh, pXsl, pW2h, pW2l, CCH, sX, sW,
        nullptr, 0, pKh, pKl, sX, CCH, pB2, CCH, nullptr);
    //    Vt = w3 Xss_t^T + b3[m] (fp16 2-term) -> single fp16 out
    hgemm16<8,1><<<dim3(HW/128, CCH/128, BATCH), 128, SMEM3>>>(
        pw3h, pw3l, pXsf, CCH, 0, sX,
        nullptr, 0, pVf, sV, HW, b3, 0, nullptr, 0);

    // 5) scores = Q K^T (fp32 out + rowmax atomics)
    hgemm<7><<<dim3(HW/128, HW/128, BATCH), 128, SMEM4>>>(
        pQh, pQl, pKh, pKl, CCH, sX, sX,
        pS, sS, nullptr, nullptr, 0, HW, nullptr, 0, pM);

    // 6) streaming softmax -> fp16 A (normalized)
    softmax_stream<<<BATCH * HW, 256>>>(pS, pM, pAf);

    // 7) O = A Vt^T (single-term fp16) -> O fp16
    hgemm16<6,2><<<dim3(CCH/128, HW/128, BATCH), 128, SMEM2>>>(
        pAf, nullptr, pVf, HW, sS, sV,
        nullptr, 0, pOf, sX, CCH, nullptr, 0, nullptr, 0);

    // 8) out = Wrs O^T + brs[m] + x_fcc (fp16 2-term, fp32 out)
    hgemm16<4,1><<<dim3(HW/128, CCH/128, BATCH), 128, SMEM3>>>(
        pwrh, pwrl, pOf, CCH, 0, sX,
        out, (size_t)CCH * HW, nullptr, 0, HW, brs, 0, x_fcc, (size_t)CCH * HW);
}

// round 13
// speedup vs baseline: 1.0032x; 1.0032x over previous
#include <cuda_runtime.h>
#include <cuda_bf16.h>
#include <cuda_fp16.h>
#include <math.h>
#include <stdint.h>

#define BATCH 4
#define CCH   512
#define HW    4096

typedef __nv_bfloat16 bf16;
typedef __half fp16;

// ---------------- scratch (static __device__ — no allocation allowed) -------
__device__ float g_mean_cc[BATCH*CCH];
__device__ float g_inv_cc [BATCH*CCH];
__device__ float g_mean_ss[BATCH*CCH];
__device__ float g_inv_ss [BATCH*CCH];
__device__ float g_b1p[BATCH*CCH];
__device__ float g_b2p[BATCH*CCH];
__device__ float g_M  [BATCH*HW];        // per-row score max

__device__ bf16 g_W1h[BATCH*CCH*CCH], g_W1l[BATCH*CCH*CCH];
__device__ bf16 g_W2h[BATCH*CCH*CCH], g_W2l[BATCH*CCH*CCH];
__device__ fp16 g_w3h[CCH*CCH],       g_w3l[CCH*CCH];
__device__ fp16 g_wrh[CCH*CCH],       g_wrl[CCH*CCH];

__device__ bf16 g_Xch[(size_t)BATCH*HW*CCH], g_Xcl[(size_t)BATCH*HW*CCH];
__device__ bf16 g_Xsh[(size_t)BATCH*HW*CCH], g_Xsl[(size_t)BATCH*HW*CCH];
__device__ fp16 g_Xsf[(size_t)BATCH*HW*CCH];
__device__ bf16 g_Qh [(size_t)BATCH*HW*CCH], g_Ql [(size_t)BATCH*HW*CCH];
__device__ bf16 g_Kh [(size_t)BATCH*HW*CCH], g_Kl [(size_t)BATCH*HW*CCH];
__device__ fp16 g_Vf [(size_t)BATCH*CCH*HW];                 // V^T fp16 single
__device__ fp16 g_Of [(size_t)BATCH*HW*CCH];                 // O fp16
__device__ fp16 g_Af [(size_t)BATCH*HW*HW];                  // softmax(A) fp16
__device__ float g_S [(size_t)BATCH*HW*HW];                  // fp32 scores

// ---------------- small helpers ----------------------------------------------
__device__ __forceinline__ float warpSum(float v) {
    #pragma unroll
    for (int o = 16; o > 0; o >>= 1) v += __shfl_down_sync(0xffffffffu, v, o);
    return v;
}
__device__ __forceinline__ uint32_t smem_u32(const void* p) {
    uint32_t a;
    asm("{ .reg .u64 t; cvta.to.shared.u64 t, %1; cvt.u32.u64 %0, t; }" : "=r"(a) : "l"(p));
    return a;
}
__device__ __forceinline__ void split_bf16(float v, bf16 &hi, bf16 &lo) {
    hi = __float2bfloat16_rn(v);
    lo = __float2bfloat16_rn(v - __bfloat162float(hi));
}
__device__ __forceinline__ void split_fp16(float v, fp16 &hi, fp16 &lo) {
    hi = __float2half_rn(v);
    lo = __float2half_rn(v - __half2float(hi));
}
__device__ __forceinline__ void atomMaxF(float* a, float v) {
    if (v >= 0.f) atomicMax((int*)a, __float_as_int(v));
    else          atomicMin((unsigned int*)a, __float_as_uint(v));
}

// ---------------- MMA primitives (baseline PTX, no 'a' features) -------------
__device__ __forceinline__ void ldsm4(uint32_t* r, uint32_t addr) {
    asm volatile("ldmatrix.sync.aligned.m8n8.x4.shared.b16 {%0,%1,%2,%3}, [%4];"
        : "=r"(r[0]), "=r"(r[1]), "=r"(r[2]), "=r"(r[3]) : "r"(addr));
}
__device__ __forceinline__ void mma_bf16(float* c, const uint32_t* a,
                                         uint32_t b0, uint32_t b1) {
    asm volatile(
        "mma.sync.aligned.m16n8k16.row.col.f32.bf16.bf16.f32 "
        "{%0,%1,%2,%3}, {%4,%5,%6,%7}, {%8,%9}, {%0,%1,%2,%3};"
        : "+f"(c[0]), "+f"(c[1]), "+f"(c[2]), "+f"(c[3])
        : "r"(a[0]), "r"(a[1]), "r"(a[2]), "r"(a[3]), "r"(b0), "r"(b1));
}
__device__ __forceinline__ void mma_fp16(float* c, const uint32_t* a,
                                         uint32_t b0, uint32_t b1) {
    asm volatile(
        "mma.sync.aligned.m16n8k16.row.col.f32.f16.f16.f32 "
        "{%0,%1,%2,%3}, {%4,%5,%6,%7}, {%8,%9}, {%0,%1,%2,%3};"
        : "+f"(c[0]), "+f"(c[1]), "+f"(c[2]), "+f"(c[3])
        : "r"(a[0]), "r"(a[1]), "r"(a[2]), "r"(a[3]), "r"(b0), "r"(b1));
}
__device__ __forceinline__ void cp16(uint32_t saddr, const void* g) {
    asm volatile("cp.async.cg.shared.global [%0], [%1], 16;"
                 :: "r"(saddr), "l"(g) : "memory");
}
#define CP_COMMIT() asm volatile("cp.async.commit_group;" ::: "memory")
#define CP_WAIT0()  asm volatile("cp.async.wait_group 0;" ::: "memory")
#define CP_WAIT1()  asm volatile("cp.async.wait_group 1;" ::: "memory")

// ---------------- instance-norm stats ---------------------------------------
__global__ __launch_bounds__(256) void stats_kernel(
    const float* __restrict__ x, float* __restrict__ mean, float* __restrict__ inv)
{
    int row = blockIdx.x;
    const float* p = x + (size_t)row * HW;
    float s = 0.f, sq = 0.f;
    for (int i = threadIdx.x; i < HW; i += 256) { float v = p[i]; s += v; sq += v * v; }
    s = warpSum(s); sq = warpSum(sq);
    __shared__ float ss[8], ssq[8];
    int w = threadIdx.x >> 5, lane = threadIdx.x & 31;
    if (lane == 0) { ss[w] = s; ssq[w] = sq; }
    __syncthreads();
    if (threadIdx.x == 0) {
        float S = 0.f, SQ = 0.f;
        #pragma unroll
        for (int i = 0; i < 8; i++) { S += ss[i]; SQ += ssq[i]; }
        float m = S / (float)HW;
        float var = (SQ - (float)HW * m * m) / (float)(HW - 1);
        mean[row] = m;
        inv[row]  = rsqrtf(var + 1e-5f);
    }
}

// ---------------- fold inst-norm into conv weights ---------------------------
__global__ __launch_bounds__(128) void fold_kernel(
    const float* __restrict__ W, const float* __restrict__ bias,
    const float* __restrict__ mean, const float* __restrict__ inv,
    bf16* __restrict__ Wh, bf16* __restrict__ Wl, float* __restrict__ bp)
{
    int o = blockIdx.x, b = blockIdx.y;
    const float* mr = mean + b * CCH;
    const float* ir = inv  + b * CCH;
    float part = 0.f;
    for (int c = threadIdx.x; c < CCH; c += 128) {
        float w  = W[o * CCH + c];
        float iv = ir[c];
        float wp = w * iv;
        bf16 hi, lo; split_bf16(wp, hi, lo);
        size_t idx = ((size_t)b * CCH + o) * CCH + c;
        Wh[idx] = hi; Wl[idx] = lo;
        part += w * mr[c] * iv;
    }
    part = warpSum(part);
    __shared__ float sp[4];
    int w = threadIdx.x >> 5, lane = threadIdx.x & 31;
    if (lane == 0) sp[w] = part;
    __syncthreads();
    if (threadIdx.x == 0) bp[b * CCH + o] = bias[o] - (sp[0] + sp[1] + sp[2] + sp[3]);
}

__global__ __launch_bounds__(256) void split_kernel_fp(
    const float* __restrict__ W, fp16* __restrict__ Wh, fp16* __restrict__ Wl, int n)
{
    int i = blockIdx.x * 256 + threadIdx.x;
    if (i < n) { fp16 hi, lo; split_fp16(W[i], hi, lo); Wh[i] = hi; Wl[i] = lo; }
}

__global__ __launch_bounds__(256) void init_rowmax(float* __restrict__ M) {
    M[blockIdx.x * 256 + threadIdx.x] = -INFINITY;
}

// ---------------- transpose + split ------------------------------------------
template<int FP16OUT>
__global__ __launch_bounds__(256) void transpose_split(
    const float* __restrict__ X, bf16* __restrict__ Th, bf16* __restrict__ Tl,
    fp16* __restrict__ Tf)
{
    int b = blockIdx.z;
    X  += (size_t)b * CCH * HW;
    Th += (size_t)b * HW * CCH;
    Tl += (size_t)b * HW * CCH;
    if (FP16OUT) Tf += (size_t)b * HW * CCH;
    __shared__ float t[32][33];
    int p0 = blockIdx.x * 32, c0 = blockIdx.y * 32;
    int tx = threadIdx.x & 31, ty = threadIdx.x >> 5;
    #pragma unroll
    for (int j = 0; j < 4; j++) {
        int cl = ty * 4 + j;
        t[cl][tx] = X[(size_t)(c0 + cl) * HW + p0 + tx];
    }
    __syncthreads();
    #pragma unroll
    for (int j = 0; j < 4; j++) {
        int pl = ty * 4 + j;
        float v = t[tx][pl];
        bf16 hi, lo; split_bf16(v, hi, lo);
        size_t idx = (size_t)(p0 + pl) * CCH + c0 + tx;
        Th[idx] = hi; Tl[idx] = lo;
        if (FP16OUT) Tf[idx] = __float2half_rn(v);
    }
}

// ============= GEMM geometry: block 128x128, 8 warps (2x4), warp 64x32 ======
#define KTILE 32
#define SROW  80
#define ABYTES (128 * SROW)
#define BUFB4 (4 * ABYTES)
#define SMEM4 (2 * BUFB4)            // bf16 GEMM: 2-stage, 80 KB
#define SMEM3 (3 * 3 * ABYTES)       // fp16 MODE1: 3-stage, 92 KB
#define SMEM2 (3 * 2 * ABYTES)       // fp16 MODE2: 3-stage, 61 KB

// ============= bf16 3-term NT GEMM (R11 config) =============================
// EPI: 1 bias[n] + bf16 hi/lo; 7 fp32 C + row-max atomics
template<int EPI>
__global__ __launch_bounds__(256) void hgemm(
    const bf16* __restrict__ Ah, const bf16* __restrict__ Al,
    const bf16* __restrict__ Bh, const bf16* __restrict__ Bl,
    int Kpass, size_t sA, size_t sB,
    float* __restrict__ C, size_t sC,
    bf16* __restrict__ Chi, bf16* __restrict__ Clo, size_t sCh,
    int ldc,
    const float* __restrict__ bias, size_t sBias,
    float* __restrict__ Mrow)
{
    extern __shared__ __align__(16) char smem[];
    const int tid  = threadIdx.x;
    const int wid  = tid >> 5, lane = tid & 31;
    const int wm   = wid >> 2, wn = wid & 3;
    const int bz   = blockIdx.z;
    const int m0   = blockIdx.y * 128;
    const int n0   = blockIdx.x * 128;

    const char* gAh = (const char*)(Ah + bz * sA);
    const char* gAl = (const char*)(Al + bz * sA);
    const char* gBh = (const char*)(Bh + bz * sB);
    const char* gBl = (const char*)(Bl + bz * sB);
    const size_t rowB = (size_t)Kpass * 2;

    const uint32_t sb = smem_u32(smem);
    const int ch0 = tid, ch1 = tid + 256;
    const int r0c = ch0 >> 2, c0c = (ch0 & 3) * 16;
    const int r1c = ch1 >> 2, c1c = (ch1 & 3) * 16;
    const uint32_t so0 = (uint32_t)(r0c * SROW + c0c);
    const uint32_t so1 = (uint32_t)(r1c * SROW + c1c);

    auto issue = [&](int t, int buf) {
        const size_t kb = (size_t)t * (KTILE * 2);
        const uint32_t s = sb + buf * BUFB4;
        const size_t ga0 = (size_t)(m0 + r0c) * rowB + kb + c0c;
        const size_t ga1 = (size_t)(m0 + r1c) * rowB + kb + c1c;
        const size_t gb0 = (size_t)(n0 + r0c) * rowB + kb + c0c;
        const size_t gb1 = (size_t)(n0 + r1c) * rowB + kb + c1c;
        cp16(s            + so0, gAh + ga0);
        cp16(s            + so1, gAh + ga1);
        cp16(s +   ABYTES + so0, gAl + ga0);
        cp16(s +   ABYTES + so1, gAl + ga1);
        cp16(s + 2*ABYTES + so0, gBh + gb0);
        cp16(s + 2*ABYTES + so1, gBh + gb1);
        cp16(s + 3*ABYTES + so0, gBl + gb0);
        cp16(s + 3*ABYTES + so1, gBl + gb1);
        CP_COMMIT();
    };

    float acc[4][4][4];
    #pragma unroll
    for (int i = 0; i < 4; i++)
        #pragma unroll
        for (int j = 0; j < 4; j++)
            #pragma unroll
            for (int q = 0; q < 4; q++) acc[i][j][q] = 0.f;

    const int nt = Kpass / KTILE;
    const int lr = lane & 15, lc = (lane >> 4) * 16;

    issue(0, 0);
    for (int t = 0; t < nt; t++) {
        const int buf = t & 1;
        CP_WAIT0();
        __syncthreads();
        if (t + 1 < nt) issue(t + 1, buf ^ 1);

        const uint32_t aH = sb + buf * BUFB4;
        const uint32_t aL = aH + ABYTES;
        const uint32_t bH = aH + 2 * ABYTES;
        const uint32_t bL = aH + 3 * ABYTES;

        #pragma unroll
        for (int ks = 0; ks < 2; ks++) {
            const int kof = ks * 32;
            uint32_t ah[4][4], al[4][4], bh[2][4], bl[2][4];
            #pragma unroll
            for (int mt = 0; mt < 4; mt++) {
                uint32_t off = (uint32_t)((wm * 64 + mt * 16 + lr) * SROW + kof + lc);
                ldsm4(ah[mt], aH + off);
                ldsm4(al[mt], aL + off);
            }
            #pragma unroll
            for (int p = 0; p < 2; p++) {
                uint32_t off = (uint32_t)((wn * 32 + p * 16 + lr) * SROW + kof + lc);
                ldsm4(bh[p], bH + off);
                ldsm4(bl[p], bL + off);
            }
            #pragma unroll
            for (int mt = 0; mt < 4; mt++) {
                #pragma unroll
                for (int ntl = 0; ntl < 4; ntl++) {
                    const int p = ntl >> 1, h = ntl & 1;
                    mma_bf16(acc[mt][ntl], ah[mt], bh[p][h], bh[p][h + 2]);
                    mma_bf16(acc[mt][ntl], ah[mt], bl[p][h], bl[p][h + 2]);
                    mma_bf16(acc[mt][ntl], al[mt], bh[p][h], bh[p][h + 2]);
                }
            }
        }
    }

    // ---- epilogue ----
    const int n_base = n0 + wn * 32;
    const int m_base = m0 + wm * 64;
    if (EPI == 7) {
        #pragma unroll
        for (int mt = 0; mt < 4; mt++) {
            #pragma unroll
            for (int half = 0; half < 2; half++) {
                const int m = m_base + mt * 16 + (lane >> 2) + half * 8;
                float mx = -INFINITY;
                #pragma unroll
                for (int ntl = 0; ntl < 4; ntl++) {
                    const int n = n_base + ntl * 8 + 2 * (lane & 3);
                    float v0 = acc[mt][ntl][half * 2 + 0];
                    float v1 = acc[mt][ntl][half * 2 + 1];
                    *(float2*)(C + bz * sC + (size_t)m * ldc + n) = make_float2(v0, v1);
                    mx = fmaxf(mx, fmaxf(v0, v1));
                }
                mx = fmaxf(mx, __shfl_xor_sync(0xffffffffu, mx, 1));
                mx = fmaxf(mx, __shfl_xor_sync(0xffffffffu, mx, 2));
                if ((lane & 3) == 0) atomMaxF(Mrow + (size_t)bz * HW + m, mx);
            }
        }
    } else {
        #pragma unroll
        for (int ntl = 0; ntl < 4; ntl++) {
            const int n = n_base + ntl * 8 + 2 * (lane & 3);
            float bn0 = bias[bz * sBias + n];
            float bn1 = bias[bz * sBias + n + 1];
            #pragma unroll
            for (int mt = 0; mt < 4; mt++) {
                #pragma unroll
                for (int half = 0; half < 2; half++) {
                    const int m = m_base + mt * 16 + (lane >> 2) + half * 8;
                    float v0 = acc[mt][ntl][half * 2 + 0] + bn0;
                    float v1 = acc[mt][ntl][half * 2 + 1] + bn1;
                    bf16 h0, l0, h1, l1;
                    split_bf16(v0, h0, l0); split_bf16(v1, h1, l1);
                    __nv_bfloat162 hp; hp.x = h0; hp.y = h1;
                    __nv_bfloat162 lp; lp.x = l0; lp.y = l1;
                    *(__nv_bfloat162*)(Chi + bz * sCh + (size_t)m * ldc + n) = hp;
                    *(__nv_bfloat162*)(Clo + bz * sCh + (size_t)m * ldc + n) = lp;
                }
            }
        }
    }
}

// ============= fp16 NT GEMM (3-stage ring, wait_group 1) ====================
// MODE 1: A fp16 hi/lo, B single fp16 (2 terms); MODE 2: single x single (1)
// EPI: 4 bias[m] + resid + fp32; 6 fp16 single; 8 bias[m] + fp16 single
template<int EPI, int MODE>
__global__ __launch_bounds__(256) void hgemm16(
    const fp16* __restrict__ A0, const fp16* __restrict__ A1,
    const fp16* __restrict__ B0,
    int Kpass, size_t sA, size_t sB,
    float* __restrict__ C, size_t sC,
    fp16* __restrict__ Cf, size_t sCf,
    int ldc,
    const float* __restrict__ bias, size_t sBias,
    const float* __restrict__ resid, size_t sResid)
{
    extern __shared__ __align__(16) char smem[];
    constexpr int NTILES = (MODE == 2) ? 2 : 3;
    constexpr int BUFB = NTILES * ABYTES;

    const int tid  = threadIdx.x;
    const int wid  = tid >> 5, lane = tid & 31;
    const int wm   = wid >> 2, wn = wid & 3;
    const int bz   = blockIdx.z;
    const int m0   = blockIdx.y * 128;
    const int n0   = blockIdx.x * 128;

    const char* gA0 = (const char*)(A0 + bz * sA);
    const char* gA1 = (MODE == 1) ? (const char*)(A1 + bz * sA) : nullptr;
    const char* gB0 = (const char*)(B0 + bz * sB);
    const size_t rowB = (size_t)Kpass * 2;

    const uint32_t sb = smem_u32(smem);
    const int ch0 = tid, ch1 = tid + 256;
    const int r0c = ch0 >> 2, c0c = (ch0 & 3) * 16;
    const int r1c = ch1 >> 2, c1c = (ch1 & 3) * 16;
    const uint32_t so0 = (uint32_t)(r0c * SROW + c0c);
    const uint32_t so1 = (uint32_t)(r1c * SROW + c1c);

    auto issue = [&](int t, int buf) {
        const size_t kb = (size_t)t * (KTILE * 2);
        const uint32_t s = sb + buf * BUFB;
        const size_t ga0 = (size_t)(m0 + r0c) * rowB + kb + c0c;
        const size_t ga1 = (size_t)(m0 + r1c) * rowB + kb + c1c;
        const size_t gb0 = (size_t)(n0 + r0c) * rowB + kb + c0c;
        const size_t gb1 = (size_t)(n0 + r1c) * rowB + kb + c1c;
        cp16(s + so0, gA0 + ga0);
        cp16(s + so1, gA0 + ga1);
        if (MODE == 1) {
            cp16(s +   ABYTES + so0, gA1 + ga0);
            cp16(s +   ABYTES + so1, gA1 + ga1);
            cp16(s + 2*ABYTES + so0, gB0 + gb0);
            cp16(s + 2*ABYTES + so1, gB0 + gb1);
        } else {
            cp16(s +   ABYTES + so0, gB0 + gb0);
            cp16(s +   ABYTES + so1, gB0 + gb1);
        }
        CP_COMMIT();
    };

    float acc[4][4][4];
    #pragma unroll
    for (int i = 0; i < 4; i++)
        #pragma unroll
        for (int j = 0; j < 4; j++)
            #pragma unroll
            for (int q = 0; q < 4; q++) acc[i][j][q] = 0.f;

    const int nt = Kpass / KTILE;
    const int lr = lane & 15, lc = (lane >> 4) * 16;

    // 3-stage ring: tiles t, t+1 in flight; compute t after wait_group 1
    issue(0, 0);
    issue(1, 1);
    for (int t = 0; t < nt; t++) {
        int buf = t % 3;
        CP_WAIT1();             // tile t complete; t+1 may still be in flight
        __syncthreads();        // all warps done computing tile t-1 (buf (t+2)%3)
        if (t + 2 < nt) issue(t + 2, (t + 2) % 3);

        const uint32_t s0 = sb + buf * BUFB;
        const uint32_t s1 = s0 + ABYTES;
        const uint32_t s2 = s0 + 2 * ABYTES;
        const uint32_t bT = (MODE == 1) ? s2 : s1;

        #pragma unroll
        for (int ks = 0; ks < 2; ks++) {
            const int kof = ks * 32;
            if (MODE == 1) {
                uint32_t ah[4][4], al[4][4], bf_[2][4];
                #pragma unroll
                for (int mt = 0; mt < 4; mt++) {
                    uint32_t off = (uint32_t)((wm * 64 + mt * 16 + lr) * SROW + kof + lc);
                    ldsm4(ah[mt], s0 + off);
                    ldsm4(al[mt], s1 + off);
                }
                #pragma unroll
                for (int p = 0; p < 2; p++) {
                    uint32_t off = (uint32_t)((wn * 32 + p * 16 + lr) * SROW + kof + lc);
                    ldsm4(bf_[p], bT + off);
                }
                #pragma unroll
                for (int mt = 0; mt < 4; mt++) {
                    #pragma unroll
                    for (int ntl = 0; ntl < 4; ntl++) {
                        const int p = ntl >> 1, h = ntl & 1;
                        mma_fp16(acc[mt][ntl], ah[mt], bf_[p][h], bf_[p][h + 2]);
                        mma_fp16(acc[mt][ntl], al[mt], bf_[p][h], bf_[p][h + 2]);
                    }
                }
            } else {
                uint32_t af[4][4], bf_[2][4];
                #pragma unroll
                for (int mt = 0; mt < 4; mt++) {
                    uint32_t off = (uint32_t)((wm * 64 + mt * 16 + lr) * SROW + kof + lc);
                    ldsm4(af[mt], s0 + off);
                }
                #pragma unroll
                for (int p = 0; p < 2; p++) {
                    uint32_t off = (uint32_t)((wn * 32 + p * 16 + lr) * SROW + kof + lc);
                    ldsm4(bf_[p], bT + off);
                }
                #pragma unroll
                for (int mt = 0; mt < 4; mt++) {
                    #pragma unroll
                    for (int ntl = 0; ntl < 4; ntl++) {
                        const int p = ntl >> 1, h = ntl & 1;
                        mma_fp16(acc[mt][ntl], af[mt], bf_[p][h], bf_[p][h + 2]);
                    }
                }
            }
        }
    }
    CP_WAIT0();

    // ---- epilogue ----
    const int n_base = n0 + wn * 32;
    const int m_base = m0 + wm * 64;
    #pragma unroll
    for (int ntl = 0; ntl < 4; ntl++) {
        const int n = n_base + ntl * 8 + 2 * (lane & 3);
        #pragma unroll
        for (int mt = 0; mt < 4; mt++) {
            #pragma unroll
            for (int half = 0; half < 2; half++) {
                const int m = m_base + mt * 16 + (lane >> 2) + half * 8;
                float v0 = acc[mt][ntl][half * 2 + 0];
                float v1 = acc[mt][ntl][half * 2 + 1];
                if (EPI == 4) {
                    float bm = bias[bz * sBias + m];
                    const float* rp = resid + bz * sResid + (size_t)m * ldc + n;
                    v0 += bm + rp[0]; v1 += bm + rp[1];
                    *(float2*)(C + bz * sC + (size_t)m * ldc + n) = make_float2(v0, v1);
                } else if (EPI == 8) {
                    float bm = bias[bz * sBias + m];
                    __half2 o;
                    o.x = __float2half_rn(v0 + bm); o.y = __float2half_rn(v1 + bm);
                    *(__half2*)(Cf + bz * sCf + (size_t)m * ldc + n) = o;
                } else { // EPI == 6
                    __half2 o; o.x = __float2half_rn(v0); o.y = __float2half_rn(v1);
                    *(__half2*)(Cf + bz * sCf + (size_t)m * ldc + n) = o;
                }
            }
        }
    }
}

// ---------------- streaming softmax: S fp32 + rowmax -> fp16 A ---------------
__global__ __launch_bounds__(256) void softmax_stream(
    const float* __restrict__ S, const float* __restrict__ M, fp16* __restrict__ Af)
{
    const size_t row = blockIdx.x;
    const float* p = S + row * HW;
    fp16* a = Af + row * HW;
    const float mx = M[row];
    int tid = threadIdx.x;
    float vals[16];
    float s = 0.f;
    #pragma unroll
    for (int i = 0; i < 16; i++) {
        vals[i] = __expf(p[tid + i * 256] - mx);
        s += vals[i];
    }
    s = warpSum(s);
    __shared__ float sh[8];
    int w = tid >> 5, lane = tid & 31;
    if (lane == 0) sh[w] = s;
    __syncthreads();
    if (w == 0) {
        float v = (lane < 8) ? sh[lane] : 0.f;
        v = warpSum(v);
        if (lane == 0) sh[0] = v;
    }
    __syncthreads();
    const float invs = 1.f / sh[0];
    #pragma unroll
    for (int i = 0; i < 16; i++)
        a[tid + i * 256] = __float2half_rn(vals[i] * invs);
}

// ---------------- launch -----------------------------------------------------
extern "C" void kernel_launch(void* const* d_in, const int* in_sizes, int n_in,
                              void* d_out, int out_size)
{
    const float* x_fcc = (const float*)d_in[0];
    const float* x_fss = (const float*)d_in[1];
    const float* w1  = (const float*)d_in[2];
    const float* b1  = (const float*)d_in[3];
    const float* w2  = (const float*)d_in[4];
    const float* b2  = (const float*)d_in[5];
    const float* w3  = (const float*)d_in[6];
    const float* b3  = (const float*)d_in[7];
    const float* wrs = (const float*)d_in[8];
    const float* brs = (const float*)d_in[9];
    float* out = (float*)d_out;

    #define SYM(p, s) void* p##_; cudaGetSymbolAddress(&p##_, s); auto p = (decltype(&s[0]))p##_;
    SYM(pMcc, g_mean_cc) SYM(pIcc, g_inv_cc) SYM(pMss, g_mean_ss) SYM(pIss, g_inv_ss)
    SYM(pB1, g_b1p) SYM(pB2, g_b2p) SYM(pM, g_M)
    SYM(pW1h, g_W1h) SYM(pW1l, g_W1l) SYM(pW2h, g_W2h) SYM(pW2l, g_W2l)
    SYM(pw3h, g_w3h) SYM(pw3l, g_w3l) SYM(pwrh, g_wrh) SYM(pwrl, g_wrl)
    SYM(pXch, g_Xch) SYM(pXcl, g_Xcl) SYM(pXsh, g_Xsh) SYM(pXsl, g_Xsl) SYM(pXsf, g_Xsf)
    SYM(pQh, g_Qh) SYM(pQl, g_Ql) SYM(pKh, g_Kh) SYM(pKl, g_Kl)
    SYM(pVf, g_Vf) SYM(pOf, g_Of) SYM(pAf, g_Af) SYM(pS, g_S)
    #undef SYM

    cudaFuncSetAttribute(hgemm<1>, cudaFuncAttributeMaxDynamicSharedMemorySize, SMEM4);
    cudaFuncSetAttribute(hgemm<7>, cudaFuncAttributeMaxDynamicSharedMemorySize, SMEM4);
    cudaFuncSetAttribute((const void*)hgemm16<8,1>, cudaFuncAttributeMaxDynamicSharedMemorySize, SMEM3);
    cudaFuncSetAttribute((const void*)hgemm16<4,1>, cudaFuncAttributeMaxDynamicSharedMemorySize, SMEM3);
    cudaFuncSetAttribute((const void*)hgemm16<6,2>, cudaFuncAttributeMaxDynamicSharedMemorySize, SMEM2);

    // 1) instance-norm stats + rowmax init
    stats_kernel<<<BATCH * CCH, 256>>>(x_fcc, pMcc, pIcc);
    stats_kernel<<<BATCH * CCH, 256>>>(x_fss, pMss, pIss);
    init_rowmax<<<BATCH * HW / 256, 256>>>(pM);

    // 2) fold norm into W1/W2; split w3, wrs (fp16)
    fold_kernel<<<dim3(CCH, BATCH), 128>>>(w1, b1, pMcc, pIcc, pW1h, pW1l, pB1);
    fold_kernel<<<dim3(CCH, BATCH), 128>>>(w2, b2, pMss, pIss, pW2h, pW2l, pB2);
    split_kernel_fp<<<CCH * CCH / 256, 256>>>(w3,  pw3h, pw3l, CCH * CCH);
    split_kernel_fp<<<CCH * CCH / 256, 256>>>(wrs, pwrh, pwrl, CCH * CCH);

    // 3) transpose + split inputs
    transpose_split<0><<<dim3(HW / 32, CCH / 32, BATCH), 256>>>(x_fcc, pXch, pXcl, nullptr);
    transpose_split<1><<<dim3(HW / 32, CCH / 32, BATCH), 256>>>(x_fss, pXsh, pXsl, pXsf);

    const size_t sX = (size_t)HW * CCH;
    const size_t sW = (size_t)CCH * CCH;
    const size_t sS = (size_t)HW * HW;
    const size_t sV = (size_t)CCH * HW;

    // 4) Q, K (bf16 3-term, bf16 hi/lo out)
    hgemm<1><<<dim3(CCH/128, HW/128, BATCH), 256, SMEM4>>>(
        pXch, pXcl, pW1h, pW1l, CCH, sX, sW,
        nullptr, 0, pQh, pQl, sX, CCH, pB1, CCH, nullptr);
    hgemm<1><<<dim3(CCH/128, HW/128, BATCH), 256, SMEM4>>>(
        pXsh, pXsl, pW2h, pW2l, CCH, sX, sW,
        nullptr, 0, pKh, pKl, sX, CCH, pB2, CCH, nullptr);
    //    Vt = w3 Xss_t^T + b3[m] (fp16 2-term) -> single fp16 out
    hgemm16<8,1><<<dim3(HW/128, CCH/128, BATCH), 256, SMEM3>>>(
        pw3h, pw3l, pXsf, CCH, 0, sX,
        nullptr, 0, pVf, sV, HW, b3, 0, nullptr, 0);

    // 5) scores = Q K^T (fp32 out + rowmax atomics)
    hgemm<7><<<dim3(HW/128, HW/128, BATCH), 256, SMEM4>>>(
        pQh, pQl, pKh, pKl, CCH, sX, sX,
        pS, sS, nullptr, nullptr, 0, HW, nullptr, 0, pM);

    // 6) streaming softmax -> fp16 A (normalized)
    softmax_stream<<<BATCH * HW, 256>>>(pS, pM, pAf);

    // 7) O = A Vt^T (single-term fp16) -> O fp16
    hgemm16<6,2><<<dim3(CCH/128, HW/128, BATCH), 256, SMEM2>>>(
        pAf, nullptr, pVf, HW, sS, sV,
        nullptr, 0, pOf, sX, CCH, nullptr, 0, nullptr, 0);

    // 8) out = Wrs O^T + brs[m] + x_fcc (fp16 2-term, fp32 out)
    hgemm16<4,1><<<dim3(HW/128, CCH/128, BATCH), 256, SMEM3>>>(
        pwrh, pwrl, pOf, CCH, 0, sX,
        out, (size_t)CCH * HW, nullptr, 0, HW, brs, 0, x_fcc, (size_t)CCH * HW);
}

// round 14
// speedup vs baseline: 1.0290x; 1.0257x over previous
#include <cuda_runtime.h>
#include <cuda_bf16.h>
#include <cuda_fp16.h>
#include <math.h>
#include <stdint.h>

#define BATCH 4
#define CCH   512
#define HW    4096

typedef __nv_bfloat16 bf16;
typedef __half fp16;

// ---------------- scratch (static __device__ — no allocation allowed) -------
__device__ float g_mean_cc[BATCH*CCH];
__device__ float g_inv_cc [BATCH*CCH];
__device__ float g_mean_ss[BATCH*CCH];
__device__ float g_inv_ss [BATCH*CCH];
__device__ float g_b1p[BATCH*CCH];
__device__ float g_b2p[BATCH*CCH];
__device__ float g_M  [BATCH*HW];        // per-row score max

__device__ bf16 g_W1h[BATCH*CCH*CCH], g_W1l[BATCH*CCH*CCH];
__device__ bf16 g_W2h[BATCH*CCH*CCH], g_W2l[BATCH*CCH*CCH];
__device__ fp16 g_w3h[CCH*CCH],       g_w3l[CCH*CCH];
__device__ fp16 g_wrh[CCH*CCH],       g_wrl[CCH*CCH];

__device__ bf16 g_Xch[(size_t)BATCH*HW*CCH], g_Xcl[(size_t)BATCH*HW*CCH];
__device__ bf16 g_Xsh[(size_t)BATCH*HW*CCH], g_Xsl[(size_t)BATCH*HW*CCH];
__device__ fp16 g_Xsf[(size_t)BATCH*HW*CCH];
__device__ bf16 g_Qh [(size_t)BATCH*HW*CCH], g_Ql [(size_t)BATCH*HW*CCH];
__device__ bf16 g_Kh [(size_t)BATCH*HW*CCH], g_Kl [(size_t)BATCH*HW*CCH];
__device__ fp16 g_Vf [(size_t)BATCH*CCH*HW];                 // V^T fp16 single
__device__ fp16 g_Of [(size_t)BATCH*HW*CCH];                 // O fp16
__device__ fp16 g_Af [(size_t)BATCH*HW*HW];                  // softmax(A) fp16
__device__ float g_S [(size_t)BATCH*HW*HW];                  // fp32 scores

// ---------------- small helpers ----------------------------------------------
__device__ __forceinline__ float warpSum(float v) {
    #pragma unroll
    for (int o = 16; o > 0; o >>= 1) v += __shfl_down_sync(0xffffffffu, v, o);
    return v;
}
__device__ __forceinline__ uint32_t smem_u32(const void* p) {
    uint32_t a;
    asm("{ .reg .u64 t; cvta.to.shared.u64 t, %1; cvt.u32.u64 %0, t; }" : "=r"(a) : "l"(p));
    return a;
}
__device__ __forceinline__ void split_bf16(float v, bf16 &hi, bf16 &lo) {
    hi = __float2bfloat16_rn(v);
    lo = __float2bfloat16_rn(v - __bfloat162float(hi));
}
__device__ __forceinline__ void split_fp16(float v, fp16 &hi, fp16 &lo) {
    hi = __float2half_rn(v);
    lo = __float2half_rn(v - __half2float(hi));
}
__device__ __forceinline__ void atomMaxF(float* a, float v) {
    if (v >= 0.f) atomicMax((int*)a, __float_as_int(v));
    else          atomicMin((unsigned int*)a, __float_as_uint(v));
}

// ---------------- MMA primitives (baseline PTX, no 'a' features) -------------
__device__ __forceinline__ void ldsm4(uint32_t* r, uint32_t addr) {
    asm volatile("ldmatrix.sync.aligned.m8n8.x4.shared.b16 {%0,%1,%2,%3}, [%4];"
        : "=r"(r[0]), "=r"(r[1]), "=r"(r[2]), "=r"(r[3]) : "r"(addr));
}
__device__ __forceinline__ void mma_bf16(float* c, const uint32_t* a,
                                         uint32_t b0, uint32_t b1) {
    asm volatile(
        "mma.sync.aligned.m16n8k16.row.col.f32.bf16.bf16.f32 "
        "{%0,%1,%2,%3}, {%4,%5,%6,%7}, {%8,%9}, {%0,%1,%2,%3};"
        : "+f"(c[0]), "+f"(c[1]), "+f"(c[2]), "+f"(c[3])
        : "r"(a[0]), "r"(a[1]), "r"(a[2]), "r"(a[3]), "r"(b0), "r"(b1));
}
__device__ __forceinline__ void mma_fp16(float* c, const uint32_t* a,
                                         uint32_t b0, uint32_t b1) {
    asm volatile(
        "mma.sync.aligned.m16n8k16.row.col.f32.f16.f16.f32 "
        "{%0,%1,%2,%3}, {%4,%5,%6,%7}, {%8,%9}, {%0,%1,%2,%3};"
        : "+f"(c[0]), "+f"(c[1]), "+f"(c[2]), "+f"(c[3])
        : "r"(a[0]), "r"(a[1]), "r"(a[2]), "r"(a[3]), "r"(b0), "r"(b1));
}
__device__ __forceinline__ void cp16(uint32_t saddr, const void* g) {
    asm volatile("cp.async.cg.shared.global [%0], [%1], 16;"
                 :: "r"(saddr), "l"(g) : "memory");
}
#define CP_COMMIT() asm volatile("cp.async.commit_group;" ::: "memory")
#define CP_WAIT0()  asm volatile("cp.async.wait_group 0;" ::: "memory")

// ---------------- instance-norm stats ---------------------------------------
__global__ __launch_bounds__(256) void stats_kernel(
    const float* __restrict__ x, float* __restrict__ mean, float* __restrict__ inv)
{
    int row = blockIdx.x;
    const float* p = x + (size_t)row * HW;
    float s = 0.f, sq = 0.f;
    for (int i = threadIdx.x; i < HW; i += 256) { float v = p[i]; s += v; sq += v * v; }
    s = warpSum(s); sq = warpSum(sq);
    __shared__ float ss[8], ssq[8];
    int w = threadIdx.x >> 5, lane = threadIdx.x & 31;
    if (lane == 0) { ss[w] = s; ssq[w] = sq; }
    __syncthreads();
    if (threadIdx.x == 0) {
        float S = 0.f, SQ = 0.f;
        #pragma unroll
        for (int i = 0; i < 8; i++) { S += ss[i]; SQ += ssq[i]; }
        float m = S / (float)HW;
        float var = (SQ - (float)HW * m * m) / (float)(HW - 1);
        mean[row] = m;
        inv[row]  = rsqrtf(var + 1e-5f);
    }
}

// ---------------- fold inst-norm into conv weights ---------------------------
__global__ __launch_bounds__(128) void fold_kernel(
    const float* __restrict__ W, const float* __restrict__ bias,
    const float* __restrict__ mean, const float* __restrict__ inv,
    bf16* __restrict__ Wh, bf16* __restrict__ Wl, float* __restrict__ bp)
{
    int o = blockIdx.x, b = blockIdx.y;
    const float* mr = mean + b * CCH;
    const float* ir = inv  + b * CCH;
    float part = 0.f;
    for (int c = threadIdx.x; c < CCH; c += 128) {
        float w  = W[o * CCH + c];
        float iv = ir[c];
        float wp = w * iv;
        bf16 hi, lo; split_bf16(wp, hi, lo);
        size_t idx = ((size_t)b * CCH + o) * CCH + c;
        Wh[idx] = hi; Wl[idx] = lo;
        part += w * mr[c] * iv;
    }
    part = warpSum(part);
    __shared__ float sp[4];
    int w = threadIdx.x >> 5, lane = threadIdx.x & 31;
    if (lane == 0) sp[w] = part;
    __syncthreads();
    if (threadIdx.x == 0) bp[b * CCH + o] = bias[o] - (sp[0] + sp[1] + sp[2] + sp[3]);
}

__global__ __launch_bounds__(256) void split_kernel_fp(
    const float* __restrict__ W, fp16* __restrict__ Wh, fp16* __restrict__ Wl, int n)
{
    int i = blockIdx.x * 256 + threadIdx.x;
    if (i < n) { fp16 hi, lo; split_fp16(W[i], hi, lo); Wh[i] = hi; Wl[i] = lo; }
}

__global__ __launch_bounds__(256) void init_rowmax(float* __restrict__ M) {
    M[blockIdx.x * 256 + threadIdx.x] = -INFINITY;
}

// ---------------- transpose + split ------------------------------------------
template<int FP16OUT>
__global__ __launch_bounds__(256) void transpose_split(
    const float* __restrict__ X, bf16* __restrict__ Th, bf16* __restrict__ Tl,
    fp16* __restrict__ Tf)
{
    int b = blockIdx.z;
    X  += (size_t)b * CCH * HW;
    Th += (size_t)b * HW * CCH;
    Tl += (size_t)b * HW * CCH;
    if (FP16OUT) Tf += (size_t)b * HW * CCH;
    __shared__ float t[32][33];
    int p0 = blockIdx.x * 32, c0 = blockIdx.y * 32;
    int tx = threadIdx.x & 31, ty = threadIdx.x >> 5;
    #pragma unroll
    for (int j = 0; j < 4; j++) {
        int cl = ty * 4 + j;
        t[cl][tx] = X[(size_t)(c0 + cl) * HW + p0 + tx];
    }
    __syncthreads();
    #pragma unroll
    for (int j = 0; j < 4; j++) {
        int pl = ty * 4 + j;
        float v = t[tx][pl];
        bf16 hi, lo; split_bf16(v, hi, lo);
        size_t idx = (size_t)(p0 + pl) * CCH + c0 + tx;
        Th[idx] = hi; Tl[idx] = lo;
        if (FP16OUT) Tf[idx] = __float2half_rn(v);
    }
}

// ============= GEMM geometry: block 128x128, 8 warps (2x4), warp 64x32 ======
#define KTILE 32
#define SROW  80
#define ABYTES (128 * SROW)
#define BUFB4 (4 * ABYTES)
#define SMEM4 (2 * BUFB4)
#define BUFB3 (3 * ABYTES)
#define SMEM3 (2 * BUFB3)
#define BUFB2 (2 * ABYTES)
#define SMEM2 (2 * BUFB2)

// ============= bf16 3-term NT GEMM (R11 config + B-frag prefetch) ===========
// EPI: 1 bias[n] + bf16 hi/lo; 7 fp32 C + row-max atomics
template<int EPI>
__global__ __launch_bounds__(256) void hgemm(
    const bf16* __restrict__ Ah, const bf16* __restrict__ Al,
    const bf16* __restrict__ Bh, const bf16* __restrict__ Bl,
    int Kpass, size_t sA, size_t sB,
    float* __restrict__ C, size_t sC,
    bf16* __restrict__ Chi, bf16* __restrict__ Clo, size_t sCh,
    int ldc,
    const float* __restrict__ bias, size_t sBias,
    float* __restrict__ Mrow)
{
    extern __shared__ __align__(16) char smem[];
    const int tid  = threadIdx.x;
    const int wid  = tid >> 5, lane = tid & 31;
    const int wm   = wid >> 2, wn = wid & 3;
    const int bz   = blockIdx.z;
    const int m0   = blockIdx.y * 128;
    const int n0   = blockIdx.x * 128;

    const char* gAh = (const char*)(Ah + bz * sA);
    const char* gAl = (const char*)(Al + bz * sA);
    const char* gBh = (const char*)(Bh + bz * sB);
    const char* gBl = (const char*)(Bl + bz * sB);
    const size_t rowB = (size_t)Kpass * 2;

    const uint32_t sb = smem_u32(smem);
    const int ch0 = tid, ch1 = tid + 256;
    const int r0c = ch0 >> 2, c0c = (ch0 & 3) * 16;
    const int r1c = ch1 >> 2, c1c = (ch1 & 3) * 16;
    const uint32_t so0 = (uint32_t)(r0c * SROW + c0c);
    const uint32_t so1 = (uint32_t)(r1c * SROW + c1c);

    auto issue = [&](int t, int buf) {
        const size_t kb = (size_t)t * (KTILE * 2);
        const uint32_t s = sb + buf * BUFB4;
        const size_t ga0 = (size_t)(m0 + r0c) * rowB + kb + c0c;
        const size_t ga1 = (size_t)(m0 + r1c) * rowB + kb + c1c;
        const size_t gb0 = (size_t)(n0 + r0c) * rowB + kb + c0c;
        const size_t gb1 = (size_t)(n0 + r1c) * rowB + kb + c1c;
        cp16(s            + so0, gAh + ga0);
        cp16(s            + so1, gAh + ga1);
        cp16(s +   ABYTES + so0, gAl + ga0);
        cp16(s +   ABYTES + so1, gAl + ga1);
        cp16(s + 2*ABYTES + so0, gBh + gb0);
        cp16(s + 2*ABYTES + so1, gBh + gb1);
        cp16(s + 3*ABYTES + so0, gBl + gb0);
        cp16(s + 3*ABYTES + so1, gBl + gb1);
        CP_COMMIT();
    };

    float acc[4][4][4];
    #pragma unroll
    for (int i = 0; i < 4; i++)
        #pragma unroll
        for (int j = 0; j < 4; j++)
            #pragma unroll
            for (int q = 0; q < 4; q++) acc[i][j][q] = 0.f;

    const int nt = Kpass / KTILE;
    const int lr = lane & 15, lc = (lane >> 4) * 16;
    const uint32_t bRowOff = (uint32_t)((wn * 32 + lr) * SROW + lc);

    issue(0, 0);
    for (int t = 0; t < nt; t++) {
        const int buf = t & 1;
        CP_WAIT0();
        __syncthreads();
        if (t + 1 < nt) issue(t + 1, buf ^ 1);

        const uint32_t aH = sb + buf * BUFB4;
        const uint32_t aL = aH + ABYTES;
        const uint32_t bH = aH + 2 * ABYTES;
        const uint32_t bL = aH + 3 * ABYTES;

        // B-frag double buffer: preload ks=0
        uint32_t bh[2][2][4], bl[2][2][4];
        #pragma unroll
        for (int p = 0; p < 2; p++) {
            uint32_t off = bRowOff + (uint32_t)(p * 16 * SROW);
            ldsm4(bh[0][p], bH + off);
            ldsm4(bl[0][p], bL + off);
        }

        #pragma unroll
        for (int ks = 0; ks < 2; ks++) {
            const int cur = ks & 1;
            if (ks + 1 < 2) {
                #pragma unroll
                for (int p = 0; p < 2; p++) {
                    uint32_t off = bRowOff + (uint32_t)(p * 16 * SROW) + 32;
                    ldsm4(bh[1][p], bH + off);
                    ldsm4(bl[1][p], bL + off);
                }
            }
            const int kof = ks * 32;
            #pragma unroll
            for (int mt = 0; mt < 4; mt++) {
                uint32_t ah[4], al[4];
                uint32_t off = (uint32_t)((wm * 64 + mt * 16 + lr) * SROW + kof + lc);
                ldsm4(ah, aH + off);
                ldsm4(al, aL + off);
                #pragma unroll
                for (int ntl = 0; ntl < 4; ntl++) {
                    const int p = ntl >> 1, h = ntl & 1;
                    mma_bf16(acc[mt][ntl], ah, bh[cur][p][h], bh[cur][p][h + 2]);
                    mma_bf16(acc[mt][ntl], ah, bl[cur][p][h], bl[cur][p][h + 2]);
                    mma_bf16(acc[mt][ntl], al, bh[cur][p][h], bh[cur][p][h + 2]);
                }
            }
        }
    }

    // ---- epilogue ----
    const int n_base = n0 + wn * 32;
    const int m_base = m0 + wm * 64;
    if (EPI == 7) {
        #pragma unroll
        for (int mt = 0; mt < 4; mt++) {
            #pragma unroll
            for (int half = 0; half < 2; half++) {
                const int m = m_base + mt * 16 + (lane >> 2) + half * 8;
                float mx = -INFINITY;
                #pragma unroll
                for (int ntl = 0; ntl < 4; ntl++) {
                    const int n = n_base + ntl * 8 + 2 * (lane & 3);
                    float v0 = acc[mt][ntl][half * 2 + 0];
                    float v1 = acc[mt][ntl][half * 2 + 1];
                    *(float2*)(C + bz * sC + (size_t)m * ldc + n) = make_float2(v0, v1);
                    mx = fmaxf(mx, fmaxf(v0, v1));
                }
                mx = fmaxf(mx, __shfl_xor_sync(0xffffffffu, mx, 1));
                mx = fmaxf(mx, __shfl_xor_sync(0xffffffffu, mx, 2));
                if ((lane & 3) == 0) atomMaxF(Mrow + (size_t)bz * HW + m, mx);
            }
        }
    } else {
        #pragma unroll
        for (int ntl = 0; ntl < 4; ntl++) {
            const int n = n_base + ntl * 8 + 2 * (lane & 3);
            float bn0 = bias[bz * sBias + n];
            float bn1 = bias[bz * sBias + n + 1];
            #pragma unroll
            for (int mt = 0; mt < 4; mt++) {
                #pragma unroll
                for (int half = 0; half < 2; half++) {
                    const int m = m_base + mt * 16 + (lane >> 2) + half * 8;
                    float v0 = acc[mt][ntl][half * 2 + 0] + bn0;
                    float v1 = acc[mt][ntl][half * 2 + 1] + bn1;
                    bf16 h0, l0, h1, l1;
                    split_bf16(v0, h0, l0); split_bf16(v1, h1, l1);
                    __nv_bfloat162 hp; hp.x = h0; hp.y = h1;
                    __nv_bfloat162 lp; lp.x = l0; lp.y = l1;
                    *(__nv_bfloat162*)(Chi + bz * sCh + (size_t)m * ldc + n) = hp;
                    *(__nv_bfloat162*)(Clo + bz * sCh + (size_t)m * ldc + n) = lp;
                }
            }
        }
    }
}

// ============= fp16 NT GEMM (R11 config + B-frag prefetch) ==================
// MODE 1: A fp16 hi/lo, B single fp16 (2 terms); MODE 2: single x single (1)
// EPI: 4 bias[m] + resid + fp32; 6 fp16 single; 8 bias[m] + fp16 single
template<int EPI, int MODE>
__global__ __launch_bounds__(256) void hgemm16(
    const fp16* __restrict__ A0, const fp16* __restrict__ A1,
    const fp16* __restrict__ B0,
    int Kpass, size_t sA, size_t sB,
    float* __restrict__ C, size_t sC,
    fp16* __restrict__ Cf, size_t sCf,
    int ldc,
    const float* __restrict__ bias, size_t sBias,
    const float* __restrict__ resid, size_t sResid)
{
    extern __shared__ __align__(16) char smem[];
    constexpr int NTILES = (MODE == 2) ? 2 : 3;
    constexpr int BUFB = NTILES * ABYTES;

    const int tid  = threadIdx.x;
    const int wid  = tid >> 5, lane = tid & 31;
    const int wm   = wid >> 2, wn = wid & 3;
    const int bz   = blockIdx.z;
    const int m0   = blockIdx.y * 128;
    const int n0   = blockIdx.x * 128;

    const char* gA0 = (const char*)(A0 + bz * sA);
    const char* gA1 = (MODE == 1) ? (const char*)(A1 + bz * sA) : nullptr;
    const char* gB0 = (const char*)(B0 + bz * sB);
    const size_t rowB = (size_t)Kpass * 2;

    const uint32_t sb = smem_u32(smem);
    const int ch0 = tid, ch1 = tid + 256;
    const int r0c = ch0 >> 2, c0c = (ch0 & 3) * 16;
    const int r1c = ch1 >> 2, c1c = (ch1 & 3) * 16;
    const uint32_t so0 = (uint32_t)(r0c * SROW + c0c);
    const uint32_t so1 = (uint32_t)(r1c * SROW + c1c);

    auto issue = [&](int t, int buf) {
        const size_t kb = (size_t)t * (KTILE * 2);
        const uint32_t s = sb + buf * BUFB;
        const size_t ga0 = (size_t)(m0 + r0c) * rowB + kb + c0c;
        const size_t ga1 = (size_t)(m0 + r1c) * rowB + kb + c1c;
        const size_t gb0 = (size_t)(n0 + r0c) * rowB + kb + c0c;
        const size_t gb1 = (size_t)(n0 + r1c) * rowB + kb + c1c;
        cp16(s + so0, gA0 + ga0);
        cp16(s + so1, gA0 + ga1);
        if (MODE == 1) {
            cp16(s +   ABYTES + so0, gA1 + ga0);
            cp16(s +   ABYTES + so1, gA1 + ga1);
            cp16(s + 2*ABYTES + so0, gB0 + gb0);
            cp16(s + 2*ABYTES + so1, gB0 + gb1);
        } else {
            cp16(s +   ABYTES + so0, gB0 + gb0);
            cp16(s +   ABYTES + so1, gB0 + gb1);
        }
        CP_COMMIT();
    };

    float acc[4][4][4];
    #pragma unroll
    for (int i = 0; i < 4; i++)
        #pragma unroll
        for (int j = 0; j < 4; j++)
            #pragma unroll
            for (int q = 0; q < 4; q++) acc[i][j][q] = 0.f;

    const int nt = Kpass / KTILE;
    const int lr = lane & 15, lc = (lane >> 4) * 16;
    const uint32_t bRowOff = (uint32_t)((wn * 32 + lr) * SROW + lc);

    issue(0, 0);
    for (int t = 0; t < nt; t++) {
        const int buf = t & 1;
        CP_WAIT0();
        __syncthreads();
        if (t + 1 < nt) issue(t + 1, buf ^ 1);

        const uint32_t s0 = sb + buf * BUFB;
        const uint32_t s1 = s0 + ABYTES;
        const uint32_t s2 = s0 + 2 * ABYTES;
        const uint32_t bT = (MODE == 1) ? s2 : s1;

        uint32_t bf_[2][2][4];
        #pragma unroll
        for (int p = 0; p < 2; p++) {
            uint32_t off = bRowOff + (uint32_t)(p * 16 * SROW);
            ldsm4(bf_[0][p], bT + off);
        }

        #pragma unroll
        for (int ks = 0; ks < 2; ks++) {
            const int cur = ks & 1;
            if (ks + 1 < 2) {
                #pragma unroll
                for (int p = 0; p < 2; p++) {
                    uint32_t off = bRowOff + (uint32_t)(p * 16 * SROW) + 32;
                    ldsm4(bf_[1][p], bT + off);
                }
            }
            const int kof = ks * 32;
            #pragma unroll
            for (int mt = 0; mt < 4; mt++) {
                uint32_t off = (uint32_t)((wm * 64 + mt * 16 + lr) * SROW + kof + lc);
                if (MODE == 1) {
                    uint32_t ah[4], al[4];
                    ldsm4(ah, s0 + off);
                    ldsm4(al, s1 + off);
                    #pragma unroll
                    for (int ntl = 0; ntl < 4; ntl++) {
                        const int p = ntl >> 1, h = ntl & 1;
                        mma_fp16(acc[mt][ntl], ah, bf_[cur][p][h], bf_[cur][p][h + 2]);
                        mma_fp16(acc[mt][ntl], al, bf_[cur][p][h], bf_[cur][p][h + 2]);
                    }
                } else {
                    uint32_t af[4];
                    ldsm4(af, s0 + off);
                    #pragma unroll
                    for (int ntl = 0; ntl < 4; ntl++) {
                        const int p = ntl >> 1, h = ntl & 1;
                        mma_fp16(acc[mt][ntl], af, bf_[cur][p][h], bf_[cur][p][h + 2]);
                    }
                }
            }
        }
    }

    // ---- epilogue ----
    const int n_base = n0 + wn * 32;
    const int m_base = m0 + wm * 64;
    #pragma unroll
    for (int ntl = 0; ntl < 4; ntl++) {
        const int n = n_base + ntl * 8 + 2 * (lane & 3);
        #pragma unroll
        for (int mt = 0; mt < 4; mt++) {
            #pragma unroll
            for (int half = 0; half < 2; half++) {
                const int m = m_base + mt * 16 + (lane >> 2) + half * 8;
                float v0 = acc[mt][ntl][half * 2 + 0];
                float v1 = acc[mt][ntl][half * 2 + 1];
                if (EPI == 4) {
                    float bm = bias[bz * sBias + m];
                    const float* rp = resid + bz * sResid + (size_t)m * ldc + n;
                    v0 += bm + rp[0]; v1 += bm + rp[1];
                    *(float2*)(C + bz * sC + (size_t)m * ldc + n) = make_float2(v0, v1);
                } else if (EPI == 8) {
                    float bm = bias[bz * sBias + m];
                    __half2 o;
                    o.x = __float2half_rn(v0 + bm); o.y = __float2half_rn(v1 + bm);
                    *(__half2*)(Cf + bz * sCf + (size_t)m * ldc + n) = o;
                } else { // EPI == 6
                    __half2 o; o.x = __float2half_rn(v0); o.y = __float2half_rn(v1);
                    *(__half2*)(Cf + bz * sCf + (size_t)m * ldc + n) = o;
                }
            }
        }
    }
}

// ---------------- streaming softmax: S fp32 + rowmax -> fp16 A ---------------
__global__ __launch_bounds__(256) void softmax_stream(
    const float* __restrict__ S, const float* __restrict__ M, fp16* __restrict__ Af)
{
    const size_t row = blockIdx.x;
    const float* p = S + row * HW;
    fp16* a = Af + row * HW;
    const float mx = M[row];
    int tid = threadIdx.x;
    float vals[16];
    float s = 0.f;
    #pragma unroll
    for (int i = 0; i < 16; i++) {
        vals[i] = __expf(p[tid + i * 256] - mx);
        s += vals[i];
    }
    s = warpSum(s);
    __shared__ float sh[8];
    int w = tid >> 5, lane = tid & 31;
    if (lane == 0) sh[w] = s;
    __syncthreads();
    if (w == 0) {
        float v = (lane < 8) ? sh[lane] : 0.f;
        v = warpSum(v);
        if (lane == 0) sh[0] = v;
    }
    __syncthreads();
    const float invs = 1.f / sh[0];
    #pragma unroll
    for (int i = 0; i < 16; i++)
        a[tid + i * 256] = __float2half_rn(vals[i] * invs);
}

// ---------------- launch -----------------------------------------------------
extern "C" void kernel_launch(void* const* d_in, const int* in_sizes, int n_in,
                              void* d_out, int out_size)
{
    const float* x_fcc = (const float*)d_in[0];
    const float* x_fss = (const float*)d_in[1];
    const float* w1  = (const float*)d_in[2];
    const float* b1  = (const float*)d_in[3];
    const float* w2  = (const float*)d_in[4];
    const float* b2  = (const float*)d_in[5];
    const float* w3  = (const float*)d_in[6];
    const float* b3  = (const float*)d_in[7];
    const float* wrs = (const float*)d_in[8];
    const float* brs = (const float*)d_in[9];
    float* out = (float*)d_out;

    #define SYM(p, s) void* p##_; cudaGetSymbolAddress(&p##_, s); auto p = (decltype(&s[0]))p##_;
    SYM(pMcc, g_mean_cc) SYM(pIcc, g_inv_cc) SYM(pMss, g_mean_ss) SYM(pIss, g_inv_ss)
    SYM(pB1, g_b1p) SYM(pB2, g_b2p) SYM(pM, g_M)
    SYM(pW1h, g_W1h) SYM(pW1l, g_W1l) SYM(pW2h, g_W2h) SYM(pW2l, g_W2l)
    SYM(pw3h, g_w3h) SYM(pw3l, g_w3l) SYM(pwrh, g_wrh) SYM(pwrl, g_wrl)
    SYM(pXch, g_Xch) SYM(pXcl, g_Xcl) SYM(pXsh, g_Xsh) SYM(pXsl, g_Xsl) SYM(pXsf, g_Xsf)
    SYM(pQh, g_Qh) SYM(pQl, g_Ql) SYM(pKh, g_Kh) SYM(pKl, g_Kl)
    SYM(pVf, g_Vf) SYM(pOf, g_Of) SYM(pAf, g_Af) SYM(pS, g_S)
    #undef SYM

    cudaFuncSetAttribute(hgemm<1>, cudaFuncAttributeMaxDynamicSharedMemorySize, SMEM4);
    cudaFuncSetAttribute(hgemm<7>, cudaFuncAttributeMaxDynamicSharedMemorySize, SMEM4);
    cudaFuncSetAttribute((const void*)hgemm16<8,1>, cudaFuncAttributeMaxDynamicSharedMemorySize, SMEM3);
    cudaFuncSetAttribute((const void*)hgemm16<4,1>, cudaFuncAttributeMaxDynamicSharedMemorySize, SMEM3);
    cudaFuncSetAttribute((const void*)hgemm16<6,2>, cudaFuncAttributeMaxDynamicSharedMemorySize, SMEM2);

    // 1) instance-norm stats + rowmax init
    stats_kernel<<<BATCH * CCH, 256>>>(x_fcc, pMcc, pIcc);
    stats_kernel<<<BATCH * CCH, 256>>>(x_fss, pMss, pIss);
    init_rowmax<<<BATCH * HW / 256, 256>>>(pM);

    // 2) fold norm into W1/W2; split w3, wrs (fp16)
    fold_kernel<<<dim3(CCH, BATCH), 128>>>(w1, b1, pMcc, pIcc, pW1h, pW1l, pB1);
    fold_kernel<<<dim3(CCH, BATCH), 128>>>(w2, b2, pMss, pIss, pW2h, pW2l, pB2);
    split_kernel_fp<<<CCH * CCH / 256, 256>>>(w3,  pw3h, pw3l, CCH * CCH);
    split_kernel_fp<<<CCH * CCH / 256, 256>>>(wrs, pwrh, pwrl, CCH * CCH);

    // 3) transpose + split inputs
    transpose_split<0><<<dim3(HW / 32, CCH / 32, BATCH), 256>>>(x_fcc, pXch, pXcl, nullptr);
    transpose_split<1><<<dim3(HW / 32, CCH / 32, BATCH), 256>>>(x_fss, pXsh, pXsl, pXsf);

    const size_t sX = (size_t)HW * CCH;
    const size_t sW = (size_t)CCH * CCH;
    const size_t sS = (size_t)HW * HW;
    const size_t sV = (size_t)CCH * HW;

    // 4) Q, K (bf16 3-term, bf16 hi/lo out)
    hgemm<1><<<dim3(CCH/128, HW/128, BATCH), 256, SMEM4>>>(
        pXch, pXcl, pW1h, pW1l, CCH, sX, sW,
        nullptr, 0, pQh, pQl, sX, CCH, pB1, CCH, nullptr);
    hgemm<1><<<dim3(CCH/128, HW/128, BATCH), 256, SMEM4>>>(
        pXsh, pXsl, pW2h, pW2l, CCH, sX, sW,
        nullptr, 0, pKh, pKl, sX, CCH, pB2, CCH, nullptr);
    //    Vt = w3 Xss_t^T + b3[m] (fp16 2-term) -> single fp16 out
    hgemm16<8,1><<<dim3(HW/128, CCH/128, BATCH), 256, SMEM3>>>(
        pw3h, pw3l, pXsf, CCH, 0, sX,
        nullptr, 0, pVf, sV, HW, b3, 0, nullptr, 0);

    // 5) scores = Q K^T (fp32 out + rowmax atomics)
    hgemm<7><<<dim3(HW/128, HW/128, BATCH), 256, SMEM4>>>(
        pQh, pQl, pKh, pKl, CCH, sX, sX,
        pS, sS, nullptr, nullptr, 0, HW, nullptr, 0, pM);

    // 6) streaming softmax -> fp16 A (normalized)
    softmax_stream<<<BATCH * HW, 256>>>(pS, pM, pAf);

    // 7) O = A Vt^T (single-term fp16) -> O fp16
    hgemm16<6,2><<<dim3(CCH/128, HW/128, BATCH), 256, SMEM2>>>(
        pAf, nullptr, pVf, HW, sS, sV,
        nullptr, 0, pOf, sX, CCH, nullptr, 0, nullptr, 0);

    // 8) out = Wrs O^T + brs[m] + x_fcc (fp16 2-term, fp32 out)
    hgemm16<4,1><<<dim3(HW/128, CCH/128, BATCH), 256, SMEM3>>>(
        pwrh, pwrl, pOf, CCH, 0, sX,
        out, (size_t)CCH * HW, nullptr, 0, HW, brs, 0, x_fcc, (size_t)CCH * HW);
}

// round 15
// speedup vs baseline: 1.0825x; 1.0520x over previous
#include <cuda_runtime.h>
#include <cuda_bf16.h>
#include <cuda_fp16.h>
#include <math.h>
#include <stdint.h>

#define BATCH 4
#define CCH   512
#define HW    4096

typedef __nv_bfloat16 bf16;
typedef __half fp16;

// ---------------- scratch (static __device__ — no allocation allowed) -------
__device__ float g_mean_cc[BATCH*CCH];
__device__ float g_inv_cc [BATCH*CCH];
__device__ float g_mean_ss[BATCH*CCH];
__device__ float g_inv_ss [BATCH*CCH];
__device__ float g_b1p[BATCH*CCH];
__device__ float g_b2p[BATCH*CCH];
__device__ float g_M  [BATCH*HW];        // per-row score max

__device__ bf16 g_W1h[BATCH*CCH*CCH], g_W1l[BATCH*CCH*CCH];
__device__ bf16 g_W2h[BATCH*CCH*CCH], g_W2l[BATCH*CCH*CCH];
__device__ fp16 g_w3h[CCH*CCH],       g_w3l[CCH*CCH];
__device__ fp16 g_wrh[CCH*CCH],       g_wrl[CCH*CCH];

__device__ bf16 g_Xch[(size_t)BATCH*HW*CCH], g_Xcl[(size_t)BATCH*HW*CCH];
__device__ bf16 g_Xsh[(size_t)BATCH*HW*CCH], g_Xsl[(size_t)BATCH*HW*CCH];
__device__ fp16 g_Xsf[(size_t)BATCH*HW*CCH];
__device__ bf16 g_Qh [(size_t)BATCH*HW*CCH], g_Ql [(size_t)BATCH*HW*CCH];
__device__ bf16 g_Kh [(size_t)BATCH*HW*CCH], g_Kl [(size_t)BATCH*HW*CCH];
__device__ fp16 g_Vf [(size_t)BATCH*CCH*HW];                 // V^T fp16 single
__device__ fp16 g_Of [(size_t)BATCH*HW*CCH];                 // O fp16
__device__ fp16 g_Af [(size_t)BATCH*HW*HW];                  // softmax(A) fp16
__device__ float g_S [(size_t)BATCH*HW*HW];                  // fp32 scores

// ---------------- small helpers ----------------------------------------------
__device__ __forceinline__ float warpSum(float v) {
    #pragma unroll
    for (int o = 16; o > 0; o >>= 1) v += __shfl_down_sync(0xffffffffu, v, o);
    return v;
}
__device__ __forceinline__ uint32_t smem_u32(const void* p) {
    uint32_t a;
    asm("{ .reg .u64 t; cvta.to.shared.u64 t, %1; cvt.u32.u64 %0, t; }" : "=r"(a) : "l"(p));
    return a;
}
__device__ __forceinline__ void split_bf16(float v, bf16 &hi, bf16 &lo) {
    hi = __float2bfloat16_rn(v);
    lo = __float2bfloat16_rn(v - __bfloat162float(hi));
}
__device__ __forceinline__ void split_fp16(float v, fp16 &hi, fp16 &lo) {
    hi = __float2half_rn(v);
    lo = __float2half_rn(v - __half2float(hi));
}
__device__ __forceinline__ void atomMaxF(float* a, float v) {
    if (v >= 0.f) atomicMax((int*)a, __float_as_int(v));
    else          atomicMin((unsigned int*)a, __float_as_uint(v));
}

// ---------------- MMA primitives (baseline PTX, no 'a' features) -------------
__device__ __forceinline__ void ldsm4(uint32_t* r, uint32_t addr) {
    asm volatile("ldmatrix.sync.aligned.m8n8.x4.shared.b16 {%0,%1,%2,%3}, [%4];"
        : "=r"(r[0]), "=r"(r[1]), "=r"(r[2]), "=r"(r[3]) : "r"(addr));
}
__device__ __forceinline__ void mma_bf16(float* c, const uint32_t* a,
                                         uint32_t b0, uint32_t b1) {
    asm volatile(
        "mma.sync.aligned.m16n8k16.row.col.f32.bf16.bf16.f32 "
        "{%0,%1,%2,%3}, {%4,%5,%6,%7}, {%8,%9}, {%0,%1,%2,%3};"
        : "+f"(c[0]), "+f"(c[1]), "+f"(c[2]), "+f"(c[3])
        : "r"(a[0]), "r"(a[1]), "r"(a[2]), "r"(a[3]), "r"(b0), "r"(b1));
}
__device__ __forceinline__ void mma_fp16(float* c, const uint32_t* a,
                                         uint32_t b0, uint32_t b1) {
    asm volatile(
        "mma.sync.aligned.m16n8k16.row.col.f32.f16.f16.f32 "
        "{%0,%1,%2,%3}, {%4,%5,%6,%7}, {%8,%9}, {%0,%1,%2,%3};"
        : "+f"(c[0]), "+f"(c[1]), "+f"(c[2]), "+f"(c[3])
        : "r"(a[0]), "r"(a[1]), "r"(a[2]), "r"(a[3]), "r"(b0), "r"(b1));
}
__device__ __forceinline__ void cp16(uint32_t saddr, const void* g) {
    asm volatile("cp.async.cg.shared.global [%0], [%1], 16;"
                 :: "r"(saddr), "l"(g) : "memory");
}
#define CP_COMMIT() asm volatile("cp.async.commit_group;" ::: "memory")
#define CP_WAIT0()  asm volatile("cp.async.wait_group 0;" ::: "memory")

// ---------------- instance-norm stats ---------------------------------------
__global__ __launch_bounds__(256) void stats_kernel(
    const float* __restrict__ x, float* __restrict__ mean, float* __restrict__ inv)
{
    int row = blockIdx.x;
    const float* p = x + (size_t)row * HW;
    float s = 0.f, sq = 0.f;
    for (int i = threadIdx.x; i < HW; i += 256) { float v = p[i]; s += v; sq += v * v; }
    s = warpSum(s); sq = warpSum(sq);
    __shared__ float ss[8], ssq[8];
    int w = threadIdx.x >> 5, lane = threadIdx.x & 31;
    if (lane == 0) { ss[w] = s; ssq[w] = sq; }
    __syncthreads();
    if (threadIdx.x == 0) {
        float S = 0.f, SQ = 0.f;
        #pragma unroll
        for (int i = 0; i < 8; i++) { S += ss[i]; SQ += ssq[i]; }
        float m = S / (float)HW;
        float var = (SQ - (float)HW * m * m) / (float)(HW - 1);
        mean[row] = m;
        inv[row]  = rsqrtf(var + 1e-5f);
    }
}

// ---------------- fold inst-norm into conv weights ---------------------------
__global__ __launch_bounds__(128) void fold_kernel(
    const float* __restrict__ W, const float* __restrict__ bias,
    const float* __restrict__ mean, const float* __restrict__ inv,
    bf16* __restrict__ Wh, bf16* __restrict__ Wl, float* __restrict__ bp)
{
    int o = blockIdx.x, b = blockIdx.y;
    const float* mr = mean + b * CCH;
    const float* ir = inv  + b * CCH;
    float part = 0.f;
    for (int c = threadIdx.x; c < CCH; c += 128) {
        float w  = W[o * CCH + c];
        float iv = ir[c];
        float wp = w * iv;
        bf16 hi, lo; split_bf16(wp, hi, lo);
        size_t idx = ((size_t)b * CCH + o) * CCH + c;
        Wh[idx] = hi; Wl[idx] = lo;
        part += w * mr[c] * iv;
    }
    part = warpSum(part);
    __shared__ float sp[4];
    int w = threadIdx.x >> 5, lane = threadIdx.x & 31;
    if (lane == 0) sp[w] = part;
    __syncthreads();
    if (threadIdx.x == 0) bp[b * CCH + o] = bias[o] - (sp[0] + sp[1] + sp[2] + sp[3]);
}

__global__ __launch_bounds__(256) void split_kernel_fp(
    const float* __restrict__ W, fp16* __restrict__ Wh, fp16* __restrict__ Wl, int n)
{
    int i = blockIdx.x * 256 + threadIdx.x;
    if (i < n) { fp16 hi, lo; split_fp16(W[i], hi, lo); Wh[i] = hi; Wl[i] = lo; }
}

__global__ __launch_bounds__(256) void init_rowmax(float* __restrict__ M) {
    M[blockIdx.x * 256 + threadIdx.x] = -INFINITY;
}

// ---------------- transpose + split ------------------------------------------
template<int FP16OUT>
__global__ __launch_bounds__(256) void transpose_split(
    const float* __restrict__ X, bf16* __restrict__ Th, bf16* __restrict__ Tl,
    fp16* __restrict__ Tf)
{
    int b = blockIdx.z;
    X  += (size_t)b * CCH * HW;
    Th += (size_t)b * HW * CCH;
    Tl += (size_t)b * HW * CCH;
    if (FP16OUT) Tf += (size_t)b * HW * CCH;
    __shared__ float t[32][33];
    int p0 = blockIdx.x * 32, c0 = blockIdx.y * 32;
    int tx = threadIdx.x & 31, ty = threadIdx.x >> 5;
    #pragma unroll
    for (int j = 0; j < 4; j++) {
        int cl = ty * 4 + j;
        t[cl][tx] = X[(size_t)(c0 + cl) * HW + p0 + tx];
    }
    __syncthreads();
    #pragma unroll
    for (int j = 0; j < 4; j++) {
        int pl = ty * 4 + j;
        float v = t[tx][pl];
        bf16 hi, lo; split_bf16(v, hi, lo);
        size_t idx = (size_t)(p0 + pl) * CCH + c0 + tx;
        Th[idx] = hi; Tl[idx] = lo;
        if (FP16OUT) Tf[idx] = __float2half_rn(v);
    }
}

// ============= GEMM geometry: block 128x128, 8 warps (2x4), warp 64x32 ======
#define KTILE 32
#define SROW  80
#define ABYTES (128 * SROW)
#define BUFB4 (4 * ABYTES)
#define SMEM4 (2 * BUFB4)
#define BUFB3 (3 * ABYTES)
#define SMEM3 (2 * BUFB3)
#define BUFB2 (2 * ABYTES)
#define SMEM2 (2 * BUFB2)

// ============= bf16 3-term NT GEMM (R14 config) =============================
// EPI: 1 bias[n] + bf16 hi/lo; 7 fp32 C + row-max atomics
template<int EPI>
__global__ __launch_bounds__(256) void hgemm(
    const bf16* __restrict__ Ah, const bf16* __restrict__ Al,
    const bf16* __restrict__ Bh, const bf16* __restrict__ Bl,
    int Kpass, size_t sA, size_t sB,
    float* __restrict__ C, size_t sC,
    bf16* __restrict__ Chi, bf16* __restrict__ Clo, size_t sCh,
    int ldc,
    const float* __restrict__ bias, size_t sBias,
    float* __restrict__ Mrow)
{
    extern __shared__ __align__(16) char smem[];
    const int tid  = threadIdx.x;
    const int wid  = tid >> 5, lane = tid & 31;
    const int wm   = wid >> 2, wn = wid & 3;
    const int bz   = blockIdx.z;
    const int m0   = blockIdx.y * 128;
    const int n0   = blockIdx.x * 128;

    const char* gAh = (const char*)(Ah + bz * sA);
    const char* gAl = (const char*)(Al + bz * sA);
    const char* gBh = (const char*)(Bh + bz * sB);
    const char* gBl = (const char*)(Bl + bz * sB);
    const size_t rowB = (size_t)Kpass * 2;

    const uint32_t sb = smem_u32(smem);
    const int ch0 = tid, ch1 = tid + 256;
    const int r0c = ch0 >> 2, c0c = (ch0 & 3) * 16;
    const int r1c = ch1 >> 2, c1c = (ch1 & 3) * 16;
    const uint32_t so0 = (uint32_t)(r0c * SROW + c0c);
    const uint32_t so1 = (uint32_t)(r1c * SROW + c1c);

    auto issue = [&](int t, int buf) {
        const size_t kb = (size_t)t * (KTILE * 2);
        const uint32_t s = sb + buf * BUFB4;
        const size_t ga0 = (size_t)(m0 + r0c) * rowB + kb + c0c;
        const size_t ga1 = (size_t)(m0 + r1c) * rowB + kb + c1c;
        const size_t gb0 = (size_t)(n0 + r0c) * rowB + kb + c0c;
        const size_t gb1 = (size_t)(n0 + r1c) * rowB + kb + c1c;
        cp16(s            + so0, gAh + ga0);
        cp16(s            + so1, gAh + ga1);
        cp16(s +   ABYTES + so0, gAl + ga0);
        cp16(s +   ABYTES + so1, gAl + ga1);
        cp16(s + 2*ABYTES + so0, gBh + gb0);
        cp16(s + 2*ABYTES + so1, gBh + gb1);
        cp16(s + 3*ABYTES + so0, gBl + gb0);
        cp16(s + 3*ABYTES + so1, gBl + gb1);
        CP_COMMIT();
    };

    float acc[4][4][4];
    #pragma unroll
    for (int i = 0; i < 4; i++)
        #pragma unroll
        for (int j = 0; j < 4; j++)
            #pragma unroll
            for (int q = 0; q < 4; q++) acc[i][j][q] = 0.f;

    const int nt = Kpass / KTILE;
    const int lr = lane & 15, lc = (lane >> 4) * 16;
    const uint32_t bRowOff = (uint32_t)((wn * 32 + lr) * SROW + lc);

    issue(0, 0);
    for (int t = 0; t < nt; t++) {
        const int buf = t & 1;
        CP_WAIT0();
        __syncthreads();
        if (t + 1 < nt) issue(t + 1, buf ^ 1);

        const uint32_t aH = sb + buf * BUFB4;
        const uint32_t aL = aH + ABYTES;
        const uint32_t bH = aH + 2 * ABYTES;
        const uint32_t bL = aH + 3 * ABYTES;

        uint32_t bh[2][2][4], bl[2][2][4];
        #pragma unroll
        for (int p = 0; p < 2; p++) {
            uint32_t off = bRowOff + (uint32_t)(p * 16 * SROW);
            ldsm4(bh[0][p], bH + off);
            ldsm4(bl[0][p], bL + off);
        }

        #pragma unroll
        for (int ks = 0; ks < 2; ks++) {
            const int cur = ks & 1;
            if (ks + 1 < 2) {
                #pragma unroll
                for (int p = 0; p < 2; p++) {
                    uint32_t off = bRowOff + (uint32_t)(p * 16 * SROW) + 32;
                    ldsm4(bh[1][p], bH + off);
                    ldsm4(bl[1][p], bL + off);
                }
            }
            const int kof = ks * 32;
            #pragma unroll
            for (int mt = 0; mt < 4; mt++) {
                uint32_t ah[4], al[4];
                uint32_t off = (uint32_t)((wm * 64 + mt * 16 + lr) * SROW + kof + lc);
                ldsm4(ah, aH + off);
                ldsm4(al, aL + off);
                #pragma unroll
                for (int ntl = 0; ntl < 4; ntl++) {
                    const int p = ntl >> 1, h = ntl & 1;
                    mma_bf16(acc[mt][ntl], ah, bh[cur][p][h], bh[cur][p][h + 2]);
                    mma_bf16(acc[mt][ntl], ah, bl[cur][p][h], bl[cur][p][h + 2]);
                    mma_bf16(acc[mt][ntl], al, bh[cur][p][h], bh[cur][p][h + 2]);
                }
            }
        }
    }

    // ---- epilogue ----
    const int n_base = n0 + wn * 32;
    const int m_base = m0 + wm * 64;
    if (EPI == 7) {
        #pragma unroll
        for (int mt = 0; mt < 4; mt++) {
            #pragma unroll
            for (int half = 0; half < 2; half++) {
                const int m = m_base + mt * 16 + (lane >> 2) + half * 8;
                float mx = -INFINITY;
                #pragma unroll
                for (int ntl = 0; ntl < 4; ntl++) {
                    const int n = n_base + ntl * 8 + 2 * (lane & 3);
                    float v0 = acc[mt][ntl][half * 2 + 0];
                    float v1 = acc[mt][ntl][half * 2 + 1];
                    *(float2*)(C + bz * sC + (size_t)m * ldc + n) = make_float2(v0, v1);
                    mx = fmaxf(mx, fmaxf(v0, v1));
                }
                mx = fmaxf(mx, __shfl_xor_sync(0xffffffffu, mx, 1));
                mx = fmaxf(mx, __shfl_xor_sync(0xffffffffu, mx, 2));
                if ((lane & 3) == 0) atomMaxF(Mrow + (size_t)bz * HW + m, mx);
            }
        }
    } else {
        #pragma unroll
        for (int ntl = 0; ntl < 4; ntl++) {
            const int n = n_base + ntl * 8 + 2 * (lane & 3);
            float bn0 = bias[bz * sBias + n];
            float bn1 = bias[bz * sBias + n + 1];
            #pragma unroll
            for (int mt = 0; mt < 4; mt++) {
                #pragma unroll
                for (int half = 0; half < 2; half++) {
                    const int m = m_base + mt * 16 + (lane >> 2) + half * 8;
                    float v0 = acc[mt][ntl][half * 2 + 0] + bn0;
                    float v1 = acc[mt][ntl][half * 2 + 1] + bn1;
                    bf16 h0, l0, h1, l1;
                    split_bf16(v0, h0, l0); split_bf16(v1, h1, l1);
                    __nv_bfloat162 hp; hp.x = h0; hp.y = h1;
                    __nv_bfloat162 lp; lp.x = l0; lp.y = l1;
                    *(__nv_bfloat162*)(Chi + bz * sCh + (size_t)m * ldc + n) = hp;
                    *(__nv_bfloat162*)(Clo + bz * sCh + (size_t)m * ldc + n) = lp;
                }
            }
        }
    }
}

// ============= fp16 NT GEMM (R14 config) ====================================
// MODE 1: A fp16 hi/lo, B single fp16 (2 terms); MODE 2: single x single (1)
// EPI: 4 bias[m] + resid + fp32; 6 fp16 single; 8 bias[m] + fp16 single
template<int EPI, int MODE>
__global__ __launch_bounds__(256) void hgemm16(
    const fp16* __restrict__ A0, const fp16* __restrict__ A1,
    const fp16* __restrict__ B0,
    int Kpass, size_t sA, size_t sB,
    float* __restrict__ C, size_t sC,
    fp16* __restrict__ Cf, size_t sCf,
    int ldc,
    const float* __restrict__ bias, size_t sBias,
    const float* __restrict__ resid, size_t sResid)
{
    extern __shared__ __align__(16) char smem[];
    constexpr int NTILES = (MODE == 2) ? 2 : 3;
    constexpr int BUFB = NTILES * ABYTES;

    const int tid  = threadIdx.x;
    const int wid  = tid >> 5, lane = tid & 31;
    const int wm   = wid >> 2, wn = wid & 3;
    const int bz   = blockIdx.z;
    const int m0   = blockIdx.y * 128;
    const int n0   = blockIdx.x * 128;

    const char* gA0 = (const char*)(A0 + bz * sA);
    const char* gA1 = (MODE == 1) ? (const char*)(A1 + bz * sA) : nullptr;
    const char* gB0 = (const char*)(B0 + bz * sB);
    const size_t rowB = (size_t)Kpass * 2;

    const uint32_t sb = smem_u32(smem);
    const int ch0 = tid, ch1 = tid + 256;
    const int r0c = ch0 >> 2, c0c = (ch0 & 3) * 16;
    const int r1c = ch1 >> 2, c1c = (ch1 & 3) * 16;
    const uint32_t so0 = (uint32_t)(r0c * SROW + c0c);
    const uint32_t so1 = (uint32_t)(r1c * SROW + c1c);

    auto issue = [&](int t, int buf) {
        const size_t kb = (size_t)t * (KTILE * 2);
        const uint32_t s = sb + buf * BUFB;
        const size_t ga0 = (size_t)(m0 + r0c) * rowB + kb + c0c;
        const size_t ga1 = (size_t)(m0 + r1c) * rowB + kb + c1c;
        const size_t gb0 = (size_t)(n0 + r0c) * rowB + kb + c0c;
        const size_t gb1 = (size_t)(n0 + r1c) * rowB + kb + c1c;
        cp16(s + so0, gA0 + ga0);
        cp16(s + so1, gA0 + ga1);
        if (MODE == 1) {
            cp16(s +   ABYTES + so0, gA1 + ga0);
            cp16(s +   ABYTES + so1, gA1 + ga1);
            cp16(s + 2*ABYTES + so0, gB0 + gb0);
            cp16(s + 2*ABYTES + so1, gB0 + gb1);
        } else {
            cp16(s +   ABYTES + so0, gB0 + gb0);
            cp16(s +   ABYTES + so1, gB0 + gb1);
        }
        CP_COMMIT();
    };

    float acc[4][4][4];
    #pragma unroll
    for (int i = 0; i < 4; i++)
        #pragma unroll
        for (int j = 0; j < 4; j++)
            #pragma unroll
            for (int q = 0; q < 4; q++) acc[i][j][q] = 0.f;

    const int nt = Kpass / KTILE;
    const int lr = lane & 15, lc = (lane >> 4) * 16;
    const uint32_t bRowOff = (uint32_t)((wn * 32 + lr) * SROW + lc);

    issue(0, 0);
    for (int t = 0; t < nt; t++) {
        const int buf = t & 1;
        CP_WAIT0();
        __syncthreads();
        if (t + 1 < nt) issue(t + 1, buf ^ 1);

        const uint32_t s0 = sb + buf * BUFB;
        const uint32_t s1 = s0 + ABYTES;
        const uint32_t s2 = s0 + 2 * ABYTES;
        const uint32_t bT = (MODE == 1) ? s2 : s1;

        uint32_t bf_[2][2][4];
        #pragma unroll
        for (int p = 0; p < 2; p++) {
            uint32_t off = bRowOff + (uint32_t)(p * 16 * SROW);
            ldsm4(bf_[0][p], bT + off);
        }

        #pragma unroll
        for (int ks = 0; ks < 2; ks++) {
            const int cur = ks & 1;
            if (ks + 1 < 2) {
                #pragma unroll
                for (int p = 0; p < 2; p++) {
                    uint32_t off = bRowOff + (uint32_t)(p * 16 * SROW) + 32;
                    ldsm4(bf_[1][p], bT + off);
                }
            }
            const int kof = ks * 32;
            #pragma unroll
            for (int mt = 0; mt < 4; mt++) {
                uint32_t off = (uint32_t)((wm * 64 + mt * 16 + lr) * SROW + kof + lc);
                if (MODE == 1) {
                    uint32_t ah[4], al[4];
                    ldsm4(ah, s0 + off);
                    ldsm4(al, s1 + off);
                    #pragma unroll
                    for (int ntl = 0; ntl < 4; ntl++) {
                        const int p = ntl >> 1, h = ntl & 1;
                        mma_fp16(acc[mt][ntl], ah, bf_[cur][p][h], bf_[cur][p][h + 2]);
                        mma_fp16(acc[mt][ntl], al, bf_[cur][p][h], bf_[cur][p][h + 2]);
                    }
                } else {
                    uint32_t af[4];
                    ldsm4(af, s0 + off);
                    #pragma unroll
                    for (int ntl = 0; ntl < 4; ntl++) {
                        const int p = ntl >> 1, h = ntl & 1;
                        mma_fp16(acc[mt][ntl], af, bf_[cur][p][h], bf_[cur][p][h + 2]);
                    }
                }
            }
        }
    }

    // ---- epilogue ----
    const int n_base = n0 + wn * 32;
    const int m_base = m0 + wm * 64;
    #pragma unroll
    for (int ntl = 0; ntl < 4; ntl++) {
        const int n = n_base + ntl * 8 + 2 * (lane & 3);
        #pragma unroll
        for (int mt = 0; mt < 4; mt++) {
            #pragma unroll
            for (int half = 0; half < 2; half++) {
                const int m = m_base + mt * 16 + (lane >> 2) + half * 8;
                float v0 = acc[mt][ntl][half * 2 + 0];
                float v1 = acc[mt][ntl][half * 2 + 1];
                if (EPI == 4) {
                    float bm = bias[bz * sBias + m];
                    const float* rp = resid + bz * sResid + (size_t)m * ldc + n;
                    v0 += bm + rp[0]; v1 += bm + rp[1];
                    *(float2*)(C + bz * sC + (size_t)m * ldc + n) = make_float2(v0, v1);
                } else if (EPI == 8) {
                    float bm = bias[bz * sBias + m];
                    __half2 o;
                    o.x = __float2half_rn(v0 + bm); o.y = __float2half_rn(v1 + bm);
                    *(__half2*)(Cf + bz * sCf + (size_t)m * ldc + n) = o;
                } else { // EPI == 6
                    __half2 o; o.x = __float2half_rn(v0); o.y = __float2half_rn(v1);
                    *(__half2*)(Cf + bz * sCf + (size_t)m * ldc + n) = o;
                }
            }
        }
    }
}

// ---------------- streaming softmax: S fp32 + rowmax -> fp16 A ---------------
__global__ __launch_bounds__(256) void softmax_stream(
    const float* __restrict__ S, const float* __restrict__ M, fp16* __restrict__ Af)
{
    const size_t row = blockIdx.x;
    const float* p = S + row * HW;
    fp16* a = Af + row * HW;
    const float mx = M[row];
    int tid = threadIdx.x;
    float vals[16];
    float s = 0.f;
    #pragma unroll
    for (int i = 0; i < 16; i++) {
        vals[i] = __expf(p[tid + i * 256] - mx);
        s += vals[i];
    }
    s = warpSum(s);
    __shared__ float sh[8];
    int w = tid >> 5, lane = tid & 31;
    if (lane == 0) sh[w] = s;
    __syncthreads();
    if (w == 0) {
        float v = (lane < 8) ? sh[lane] : 0.f;
        v = warpSum(v);
        if (lane == 0) sh[0] = v;
    }
    __syncthreads();
    const float invs = 1.f / sh[0];
    #pragma unroll
    for (int i = 0; i < 16; i++)
        a[tid + i * 256] = __float2half_rn(vals[i] * invs);
}

// ---------------- launch -----------------------------------------------------
extern "C" void kernel_launch(void* const* d_in, const int* in_sizes, int n_in,
                              void* d_out, int out_size)
{
    const float* x_fcc = (const float*)d_in[0];
    const float* x_fss = (const float*)d_in[1];
    const float* w1  = (const float*)d_in[2];
    const float* b1  = (const float*)d_in[3];
    const float* w2  = (const float*)d_in[4];
    const float* b2  = (const float*)d_in[5];
    const float* w3  = (const float*)d_in[6];
    const float* b3  = (const float*)d_in[7];
    const float* wrs = (const float*)d_in[8];
    const float* brs = (const float*)d_in[9];
    float* out = (float*)d_out;

    #define SYM(p, s) void* p##_; cudaGetSymbolAddress(&p##_, s); auto p = (decltype(&s[0]))p##_;
    SYM(pMcc, g_mean_cc) SYM(pIcc, g_inv_cc) SYM(pMss, g_mean_ss) SYM(pIss, g_inv_ss)
    SYM(pB1, g_b1p) SYM(pB2, g_b2p) SYM(pM, g_M)
    SYM(pW1h, g_W1h) SYM(pW1l, g_W1l) SYM(pW2h, g_W2h) SYM(pW2l, g_W2l)
    SYM(pw3h, g_w3h) SYM(pw3l, g_w3l) SYM(pwrh, g_wrh) SYM(pwrl, g_wrl)
    SYM(pXch, g_Xch) SYM(pXcl, g_Xcl) SYM(pXsh, g_Xsh) SYM(pXsl, g_Xsl) SYM(pXsf, g_Xsf)
    SYM(pQh, g_Qh) SYM(pQl, g_Ql) SYM(pKh, g_Kh) SYM(pKl, g_Kl)
    SYM(pVf, g_Vf) SYM(pOf, g_Of) SYM(pAf, g_Af) SYM(pS, g_S)
    #undef SYM

    // streams/events: created on first (uncaptured correctness) call, reused after
    static cudaStream_t st1 = nullptr, st2 = nullptr;
    static cudaEvent_t eFork, eTss, eK, eV, eInit;
    if (!st1) {
        cudaStreamCreateWithFlags(&st1, cudaStreamNonBlocking);
        cudaStreamCreateWithFlags(&st2, cudaStreamNonBlocking);
        cudaEventCreateWithFlags(&eFork, cudaEventDisableTiming);
        cudaEventCreateWithFlags(&eTss,  cudaEventDisableTiming);
        cudaEventCreateWithFlags(&eK,    cudaEventDisableTiming);
        cudaEventCreateWithFlags(&eV,    cudaEventDisableTiming);
        cudaEventCreateWithFlags(&eInit, cudaEventDisableTiming);
        cudaFuncSetAttribute(hgemm<1>, cudaFuncAttributeMaxDynamicSharedMemorySize, SMEM4);
        cudaFuncSetAttribute(hgemm<7>, cudaFuncAttributeMaxDynamicSharedMemorySize, SMEM4);
        cudaFuncSetAttribute((const void*)hgemm16<8,1>, cudaFuncAttributeMaxDynamicSharedMemorySize, SMEM3);
        cudaFuncSetAttribute((const void*)hgemm16<4,1>, cudaFuncAttributeMaxDynamicSharedMemorySize, SMEM3);
        cudaFuncSetAttribute((const void*)hgemm16<6,2>, cudaFuncAttributeMaxDynamicSharedMemorySize, SMEM2);
    }

    const size_t sX = (size_t)HW * CCH;
    const size_t sW = (size_t)CCH * CCH;
    const size_t sS = (size_t)HW * HW;
    const size_t sV = (size_t)CCH * HW;

    // ---- fork ----
    cudaEventRecord(eFork, 0);
    cudaStreamWaitEvent(st1, eFork, 0);
    cudaStreamWaitEvent(st2, eFork, 0);

    // ---- main stream (s0): content chain -> Q, then attention tail ----
    init_rowmax<<<BATCH * HW / 256, 256, 0, 0>>>(pM);
    cudaEventRecord(eInit, 0);
    stats_kernel<<<BATCH * CCH, 256, 0, 0>>>(x_fcc, pMcc, pIcc);
    fold_kernel<<<dim3(CCH, BATCH), 128, 0, 0>>>(w1, b1, pMcc, pIcc, pW1h, pW1l, pB1);
    transpose_split<0><<<dim3(HW / 32, CCH / 32, BATCH), 256, 0, 0>>>(x_fcc, pXch, pXcl, nullptr);
    hgemm<1><<<dim3(CCH/128, HW/128, BATCH), 256, SMEM4, 0>>>(
        pXch, pXcl, pW1h, pW1l, CCH, sX, sW,
        nullptr, 0, pQh, pQl, sX, CCH, pB1, CCH, nullptr);

    // ---- stream 1: style chain -> K ----
    stats_kernel<<<BATCH * CCH, 256, 0, st1>>>(x_fss, pMss, pIss);
    fold_kernel<<<dim3(CCH, BATCH), 128, 0, st1>>>(w2, b2, pMss, pIss, pW2h, pW2l, pB2);
    transpose_split<1><<<dim3(HW / 32, CCH / 32, BATCH), 256, 0, st1>>>(x_fss, pXsh, pXsl, pXsf);
    cudaEventRecord(eTss, st1);
    hgemm<1><<<dim3(CCH/128, HW/128, BATCH), 256, SMEM4, st1>>>(
        pXsh, pXsl, pW2h, pW2l, CCH, sX, sW,
        nullptr, 0, pKh, pKl, sX, CCH, pB2, CCH, nullptr);
    cudaEventRecord(eK, st1);

    // ---- stream 2: weight splits -> V ----
    split_kernel_fp<<<CCH * CCH / 256, 256, 0, st2>>>(w3,  pw3h, pw3l, CCH * CCH);
    split_kernel_fp<<<CCH * CCH / 256, 256, 0, st2>>>(wrs, pwrh, pwrl, CCH * CCH);
    cudaStreamWaitEvent(st2, eTss, 0);
    hgemm16<8,1><<<dim3(HW/128, CCH/128, BATCH), 256, SMEM3, st2>>>(
        pw3h, pw3l, pXsf, CCH, 0, sX,
        nullptr, 0, pVf, sV, HW, b3, 0, nullptr, 0);
    cudaEventRecord(eV, st2);

    // ---- join: scores needs Q (s0), K (st1), rowmax init (eInit via s0 order) ----
    cudaStreamWaitEvent(0, eK, 0);
    hgemm<7><<<dim3(HW/128, HW/128, BATCH), 256, SMEM4, 0>>>(
        pQh, pQl, pKh, pKl, CCH, sX, sX,
        pS, sS, nullptr, nullptr, 0, HW, nullptr, 0, pM);

    // softmax -> fp16 A
    softmax_stream<<<BATCH * HW, 256, 0, 0>>>(pS, pM, pAf);

    // AV needs V (st2)
    cudaStreamWaitEvent(0, eV, 0);
    hgemm16<6,2><<<dim3(CCH/128, HW/128, BATCH), 256, SMEM2, 0>>>(
        pAf, nullptr, pVf, HW, sS, sV,
        nullptr, 0, pOf, sX, CCH, nullptr, 0, nullptr, 0);

    // final conv + bias + residual (wrs split done on st2 before eV)
    hgemm16<4,1><<<dim3(HW/128, CCH/128, BATCH), 256, SMEM3, 0>>>(
        pwrh, pwrl, pOf, CCH, 0, sX,
        out, (size_t)CCH * HW, nullptr, 0, HW, brs, 0, x_fcc, (size_t)CCH * HW);

    (void)eInit;
}